// round 2
// baseline (speedup 1.0000x reference)
#include <cuda_runtime.h>
#include <cuda_bf16.h>
#include <cstdint>

// Problem constants
#define B_   2
#define L_   2048
#define HID_ 2048
#define H_   32
#define KVH_ 8
#define D_   64

// ---------------------------------------------------------------------------
// Scratch (static device arrays; no allocation allowed)
// ---------------------------------------------------------------------------
__device__ float g_q  [(size_t)B_ * L_ * H_   * D_];   // 8.4M
__device__ float g_k  [(size_t)B_ * L_ * KVH_ * D_];   // 2.1M
__device__ float g_v  [(size_t)B_ * L_ * KVH_ * D_];   // 2.1M
__device__ float g_att[(size_t)B_ * L_ * H_   * D_];   // 8.4M

// ---------------------------------------------------------------------------
// NT GEMM: C[M,N] = A[M,K] * B[N,K]^T   (both A and B are K-contiguous)
// 128x128x16 tiles, 256 threads, 8x8 per-thread micro-tile.
// All dims here are multiples of the tile sizes (M=4096, N in {512,2048}, K=2048).
// ---------------------------------------------------------------------------
__global__ __launch_bounds__(256) void gemm_nt(
    const float* __restrict__ A, const float* __restrict__ Bm,
    float* __restrict__ C, int M, int N, int K)
{
    __shared__ float As[16][128];
    __shared__ float Bs[16][128];

    const int tid = threadIdx.x;
    const int tx  = tid & 15;
    const int ty  = tid >> 4;
    const int bm  = blockIdx.y * 128;
    const int bn  = blockIdx.x * 128;

    const float* Ag = A  + (size_t)bm * K;
    const float* Bg = Bm + (size_t)bn * K;

    float acc[8][8];
#pragma unroll
    for (int i = 0; i < 8; i++)
#pragma unroll
        for (int j = 0; j < 8; j++) acc[i][j] = 0.0f;

    for (int k0 = 0; k0 < K; k0 += 16) {
#pragma unroll
        for (int i = 0; i < 2; i++) {
            int idx = (tid + i * 256) << 2;   // 0..2044, step 4
            int row = idx >> 4;               // 0..127
            int kk  = idx & 15;               // 0,4,8,12
            float4 va = *(const float4*)(Ag + (size_t)row * K + k0 + kk);
            As[kk + 0][row] = va.x;
            As[kk + 1][row] = va.y;
            As[kk + 2][row] = va.z;
            As[kk + 3][row] = va.w;
            float4 vb = *(const float4*)(Bg + (size_t)row * K + k0 + kk);
            Bs[kk + 0][row] = vb.x;
            Bs[kk + 1][row] = vb.y;
            Bs[kk + 2][row] = vb.z;
            Bs[kk + 3][row] = vb.w;
        }
        __syncthreads();

#pragma unroll
        for (int kk = 0; kk < 16; kk++) {
            float a[8], bv[8];
            *(float4*)&a[0]  = *(const float4*)&As[kk][ty * 8];
            *(float4*)&a[4]  = *(const float4*)&As[kk][ty * 8 + 4];
            *(float4*)&bv[0] = *(const float4*)&Bs[kk][tx * 8];
            *(float4*)&bv[4] = *(const float4*)&Bs[kk][tx * 8 + 4];
#pragma unroll
            for (int i = 0; i < 8; i++)
#pragma unroll
                for (int j = 0; j < 8; j++)
                    acc[i][j] = fmaf(a[i], bv[j], acc[i][j]);
        }
        __syncthreads();
    }

#pragma unroll
    for (int i = 0; i < 8; i++) {
        float* crow = C + (size_t)(bm + ty * 8 + i) * N + bn + tx * 8;
        *(float4*)(crow)     = make_float4(acc[i][0], acc[i][1], acc[i][2], acc[i][3]);
        *(float4*)(crow + 4) = make_float4(acc[i][4], acc[i][5], acc[i][6], acc[i][7]);
    }
}

// ---------------------------------------------------------------------------
// RoPE: interleaved pairs (d even/odd). t is [B, L, nh, D], freqs are [L, D/2].
// One thread per (b, l, h, pair) as float2.
// ---------------------------------------------------------------------------
__global__ void rope_kernel(float* __restrict__ t,
                            const float* __restrict__ fc,
                            const float* __restrict__ fs, int nh)
{
    int idx = blockIdx.x * blockDim.x + threadIdx.x;
    int total = B_ * L_ * nh * (D_ / 2);
    if (idx >= total) return;
    int p = idx & 31;                 // D/2 = 32
    int rest = idx >> 5;
    int h = rest % nh;
    rest /= nh;
    int l = rest % L_;
    int b = rest / L_;
    float c = fc[l * 32 + p];
    float s = fs[l * 32 + p];
    float2* base = (float2*)t + ((size_t)((b * L_ + l) * nh + h) * 32 + p);
    float2 v = *base;
    *base = make_float2(v.x * c - v.y * s, v.x * s + v.y * c);
}

// ---------------------------------------------------------------------------
// Causal GQA flash attention (fp32, online softmax).
// One CTA per (query block of 64, head, batch). 256 threads = 16x16 grid of
// 4x4 micro-tiles. Q/K staged TRANSPOSED in smem ([d][row]) so both S=Q*K^T
// and O+=P*V are outer products: 2x LDS.128 -> 16 FMA.
// Row softmax stats via half-warp (16-lane) shuffles — a row group is exactly
// the 16 tx lanes of one ty, which is a contiguous half-warp.
// ---------------------------------------------------------------------------
#define ATT_STRIDE 68                     // 64 + 4 pad (keeps float4 alignment)
#define SM_QS 0
#define SM_KS (64 * ATT_STRIDE)
#define SM_VS (2 * 64 * ATT_STRIDE)
#define SM_PT (3 * 64 * ATT_STRIDE)
#define SM_MS (4 * 64 * ATT_STRIDE)
#define SM_LS (4 * 64 * ATT_STRIDE + 64)
#define ATT_SMEM_FLOATS (4 * 64 * ATT_STRIDE + 128)
#define ATT_SMEM_BYTES (ATT_SMEM_FLOATS * 4)

__global__ __launch_bounds__(256) void attn_kernel()
{
    extern __shared__ float sm[];
    const int qb  = blockIdx.x;           // 0..31 (query block)
    const int h   = blockIdx.y;           // 0..31
    const int b   = blockIdx.z;           // 0..1
    const int kvh = h >> 2;               // GQA: 4 q heads per kv head
    const int tid = threadIdx.x;
    const int tx  = tid & 15;
    const int ty  = tid >> 4;
    const int r0  = ty * 4;               // query rows owned
    const int c0  = tx * 4;               // key cols / d cols owned

    // --- load Q tile transposed + scaled, init stats ---
    {
        const float* qg = g_q + ((size_t)(b * L_ + qb * 64) * H_ + h) * D_;
#pragma unroll
        for (int i = 0; i < 4; i++) {
            int f   = tid + i * 256;      // 0..1023
            int row = f >> 4;
            int dd  = (f & 15) << 2;
            float4 v = *(const float4*)(qg + (size_t)row * (H_ * D_) + dd);
            sm[SM_QS + (dd + 0) * ATT_STRIDE + row] = v.x * 0.125f;
            sm[SM_QS + (dd + 1) * ATT_STRIDE + row] = v.y * 0.125f;
            sm[SM_QS + (dd + 2) * ATT_STRIDE + row] = v.z * 0.125f;
            sm[SM_QS + (dd + 3) * ATT_STRIDE + row] = v.w * 0.125f;
        }
        if (tid < 64) {
            sm[SM_MS + tid] = -1e30f;
            sm[SM_LS + tid] = 0.0f;
        }
    }
    __syncthreads();

    float O[4][4];
#pragma unroll
    for (int i = 0; i < 4; i++)
#pragma unroll
        for (int j = 0; j < 4; j++) O[i][j] = 0.0f;

    for (int kb = 0; kb <= qb; kb++) {
        // --- load K (transposed) and V (natural) tiles ---
        const float* kg = g_k + ((size_t)(b * L_ + kb * 64) * KVH_ + kvh) * D_;
        const float* vg = g_v + ((size_t)(b * L_ + kb * 64) * KVH_ + kvh) * D_;
#pragma unroll
        for (int i = 0; i < 4; i++) {
            int f   = tid + i * 256;
            int row = f >> 4;
            int dd  = (f & 15) << 2;
            float4 kv = *(const float4*)(kg + (size_t)row * (KVH_ * D_) + dd);
            sm[SM_KS + (dd + 0) * ATT_STRIDE + row] = kv.x;
            sm[SM_KS + (dd + 1) * ATT_STRIDE + row] = kv.y;
            sm[SM_KS + (dd + 2) * ATT_STRIDE + row] = kv.z;
            sm[SM_KS + (dd + 3) * ATT_STRIDE + row] = kv.w;
            float4 vv = *(const float4*)(vg + (size_t)row * (KVH_ * D_) + dd);
            *(float4*)(sm + SM_VS + row * ATT_STRIDE + dd) = vv;
        }
        __syncthreads();

        // --- S = Q * K^T (outer product over d) ---
        float s[4][4];
#pragma unroll
        for (int i = 0; i < 4; i++)
#pragma unroll
            for (int j = 0; j < 4; j++) s[i][j] = 0.0f;

#pragma unroll 8
        for (int d = 0; d < 64; d++) {
            float4 a4 = *(const float4*)(sm + SM_QS + d * ATT_STRIDE + r0);
            float4 k4 = *(const float4*)(sm + SM_KS + d * ATT_STRIDE + c0);
            float av[4] = {a4.x, a4.y, a4.z, a4.w};
            float kv[4] = {k4.x, k4.y, k4.z, k4.w};
#pragma unroll
            for (int i = 0; i < 4; i++)
#pragma unroll
                for (int j = 0; j < 4; j++)
                    s[i][j] = fmaf(av[i], kv[j], s[i][j]);
        }

        // --- causal mask on diagonal block ---
        if (kb == qb) {
#pragma unroll
            for (int i = 0; i < 4; i++)
#pragma unroll
                for (int j = 0; j < 4; j++)
                    if (c0 + j > r0 + i) s[i][j] = -1e30f;
        }

        // --- online softmax per row (half-warp owns a row) ---
        float alpha[4];
#pragma unroll
        for (int i = 0; i < 4; i++) {
            float mx = fmaxf(fmaxf(s[i][0], s[i][1]), fmaxf(s[i][2], s[i][3]));
#pragma unroll
            for (int off = 8; off > 0; off >>= 1)
                mx = fmaxf(mx, __shfl_xor_sync(0xffffffffu, mx, off, 16));
            float mold = sm[SM_MS + r0 + i];
            float mnew = fmaxf(mold, mx);
            alpha[i] = __expf(mold - mnew);
            float sum = 0.0f;
#pragma unroll
            for (int j = 0; j < 4; j++) {
                float p = __expf(s[i][j] - mnew);
                s[i][j] = p;
                sum += p;
            }
#pragma unroll
            for (int off = 8; off > 0; off >>= 1)
                sum += __shfl_xor_sync(0xffffffffu, sum, off, 16);
            __syncwarp();
            if (tx == 0) {
                sm[SM_MS + r0 + i] = mnew;
                sm[SM_LS + r0 + i] = sm[SM_LS + r0 + i] * alpha[i] + sum;
            }
            // write P transposed: Pt[key][row]
#pragma unroll
            for (int j = 0; j < 4; j++)
                sm[SM_PT + (c0 + j) * ATT_STRIDE + (r0 + i)] = s[i][j];
        }
        __syncthreads();

        // --- O = O*alpha + P*V (outer product over keys) ---
#pragma unroll
        for (int i = 0; i < 4; i++)
#pragma unroll
            for (int j = 0; j < 4; j++) O[i][j] *= alpha[i];

#pragma unroll 8
        for (int kk = 0; kk < 64; kk++) {
            float4 p4 = *(const float4*)(sm + SM_PT + kk * ATT_STRIDE + r0);
            float4 v4 = *(const float4*)(sm + SM_VS + kk * ATT_STRIDE + c0);
            float pv[4] = {p4.x, p4.y, p4.z, p4.w};
            float vv[4] = {v4.x, v4.y, v4.z, v4.w};
#pragma unroll
            for (int i = 0; i < 4; i++)
#pragma unroll
                for (int j = 0; j < 4; j++)
                    O[i][j] = fmaf(pv[i], vv[j], O[i][j]);
        }
        __syncthreads();
    }

    // --- epilogue: normalize and store ---
    float* og = g_att + ((size_t)(b * L_ + qb * 64) * H_ + h) * D_;
#pragma unroll
    for (int i = 0; i < 4; i++) {
        float inv = 1.0f / sm[SM_LS + r0 + i];
        float4 r = make_float4(O[i][0] * inv, O[i][1] * inv,
                               O[i][2] * inv, O[i][3] * inv);
        *(float4*)(og + (size_t)(r0 + i) * (H_ * D_) + c0) = r;
    }
}

// ---------------------------------------------------------------------------
// Launch
// ---------------------------------------------------------------------------
extern "C" void kernel_launch(void* const* d_in, const int* in_sizes, int n_in,
                              void* d_out, int out_size)
{
    const float* x  = (const float*)d_in[0];
    const float* wq = (const float*)d_in[1];
    const float* wk = (const float*)d_in[2];
    const float* wv = (const float*)d_in[3];
    const float* wo = (const float*)d_in[4];
    const float* fc = (const float*)d_in[5];
    const float* fs = (const float*)d_in[6];
    // d_in[7] = mask (pure causal, folded into kernel), d_in[8] = start_pos (0)
    float* out = (float*)d_out;

    float *gq, *gk, *gv, *ga;
    cudaGetSymbolAddress((void**)&gq, g_q);
    cudaGetSymbolAddress((void**)&gk, g_k);
    cudaGetSymbolAddress((void**)&gv, g_v);
    cudaGetSymbolAddress((void**)&ga, g_att);

    const int M = B_ * L_;                       // 4096

    // QKV projections
    gemm_nt<<<dim3((H_ * D_) / 128, M / 128),   256>>>(x, wq, gq, M, H_ * D_,   HID_);
    gemm_nt<<<dim3((KVH_ * D_) / 128, M / 128), 256>>>(x, wk, gk, M, KVH_ * D_, HID_);
    gemm_nt<<<dim3((KVH_ * D_) / 128, M / 128), 256>>>(x, wv, gv, M, KVH_ * D_, HID_);

    // RoPE
    {
        int nq = B_ * L_ * H_ * (D_ / 2);
        int nk = B_ * L_ * KVH_ * (D_ / 2);
        rope_kernel<<<(nq + 255) / 256, 256>>>(gq, fc, fs, H_);
        rope_kernel<<<(nk + 255) / 256, 256>>>(gk, fc, fs, KVH_);
    }

    // Attention
    cudaFuncSetAttribute(attn_kernel, cudaFuncAttributeMaxDynamicSharedMemorySize,
                         ATT_SMEM_BYTES);
    attn_kernel<<<dim3(L_ / 64, H_, B_), 256, ATT_SMEM_BYTES>>>();

    // Output projection
    gemm_nt<<<dim3(HID_ / 128, M / 128), 256>>>(ga, wo, out, M, HID_, H_ * D_);
}

// round 3
// speedup vs baseline: 1.5774x; 1.5774x over previous
#include <cuda_runtime.h>
#include <cuda_bf16.h>
#include <cstdint>

// Problem constants
#define B_   2
#define L_   2048
#define HID_ 2048
#define H_   32
#define KVH_ 8
#define D_   64

// ---------------------------------------------------------------------------
// Scratch (static device arrays; no allocation allowed)
// ---------------------------------------------------------------------------
__device__ float g_q  [(size_t)B_ * L_ * H_   * D_];
__device__ float g_k  [(size_t)B_ * L_ * KVH_ * D_];
__device__ float g_v  [(size_t)B_ * L_ * KVH_ * D_];
__device__ float g_att[(size_t)B_ * L_ * H_   * D_];

// bf16 hi/lo split scratch
#define NX  ((size_t)B_ * L_ * HID_)          // 8.4M
#define NWQ ((size_t)H_ * D_ * HID_)          // 4.2M
#define NWK ((size_t)KVH_ * D_ * HID_)        // 1.05M
#define NWO ((size_t)HID_ * H_ * D_)          // 4.2M
__device__ __nv_bfloat16 g_xhi [NX],  g_xlo [NX];
__device__ __nv_bfloat16 g_wqhi[NWQ], g_wqlo[NWQ];
__device__ __nv_bfloat16 g_wkhi[NWK], g_wklo[NWK];
__device__ __nv_bfloat16 g_wvhi[NWK], g_wvlo[NWK];
__device__ __nv_bfloat16 g_wohi[NWO], g_wolo[NWO];
__device__ __nv_bfloat16 g_ahi [NX],  g_alo [NX];

// ---------------------------------------------------------------------------
// Split fp32 -> bf16 hi + bf16 lo (lo = rn(x - hi)). Vectorized by 4.
// ---------------------------------------------------------------------------
__global__ void split_kernel(const float* __restrict__ in,
                             __nv_bfloat16* __restrict__ hi,
                             __nv_bfloat16* __restrict__ lo, int n4)
{
    int i = blockIdx.x * blockDim.x + threadIdx.x;
    if (i >= n4) return;
    float4 v = ((const float4*)in)[i];
    __nv_bfloat16 h0 = __float2bfloat16(v.x);
    __nv_bfloat16 h1 = __float2bfloat16(v.y);
    __nv_bfloat16 h2 = __float2bfloat16(v.z);
    __nv_bfloat16 h3 = __float2bfloat16(v.w);
    __nv_bfloat16 l0 = __float2bfloat16(v.x - __bfloat162float(h0));
    __nv_bfloat16 l1 = __float2bfloat16(v.y - __bfloat162float(h1));
    __nv_bfloat16 l2 = __float2bfloat16(v.z - __bfloat162float(h2));
    __nv_bfloat16 l3 = __float2bfloat16(v.w - __bfloat162float(h3));
    ((__nv_bfloat162*)hi)[2 * i + 0] = __halves2bfloat162(h0, h1);
    ((__nv_bfloat162*)hi)[2 * i + 1] = __halves2bfloat162(h2, h3);
    ((__nv_bfloat162*)lo)[2 * i + 0] = __halves2bfloat162(l0, l1);
    ((__nv_bfloat162*)lo)[2 * i + 1] = __halves2bfloat162(l2, l3);
}

// ---------------------------------------------------------------------------
// Tensor-core NT GEMM, bf16x3 split precision:
//   C = Ahi*Bhi^T + Ahi*Blo^T + Alo*Bhi^T   (fp32 accumulate)
// A:[M,K], B:[N,K], both K-contiguous (natural mma TN layout).
// CTA 128x128, BK=32, 8 warps (4x2, warp tile 32x64), cp.async double buffer.
// smem rows padded to 40 halves (80B) -> conflict-free ldmatrix.
// ---------------------------------------------------------------------------
#define GSTG 40960           // bytes per stage (4 arrays * 128 rows * 80B)
#define GARR 10240           // bytes per array within a stage
#define GEMM_SMEM (2 * GSTG)

__device__ __forceinline__ void ldm_x4(uint32_t* r, uint32_t addr) {
    asm volatile("ldmatrix.sync.aligned.m8n8.x4.shared.b16 {%0,%1,%2,%3}, [%4];"
                 : "=r"(r[0]), "=r"(r[1]), "=r"(r[2]), "=r"(r[3]) : "r"(addr));
}
__device__ __forceinline__ void mma16816(float* d, const uint32_t* a, const uint32_t* b) {
    asm volatile("mma.sync.aligned.m16n8k16.row.col.f32.bf16.bf16.f32 "
                 "{%0,%1,%2,%3}, {%4,%5,%6,%7}, {%8,%9}, {%0,%1,%2,%3};"
                 : "+f"(d[0]), "+f"(d[1]), "+f"(d[2]), "+f"(d[3])
                 : "r"(a[0]), "r"(a[1]), "r"(a[2]), "r"(a[3]), "r"(b[0]), "r"(b[1]));
}

__global__ __launch_bounds__(256) void gemm_bf16x3(
    const __nv_bfloat16* __restrict__ Ahi, const __nv_bfloat16* __restrict__ Alo,
    const __nv_bfloat16* __restrict__ Bhi, const __nv_bfloat16* __restrict__ Blo,
    float* __restrict__ C, int M, int N, int K)
{
    extern __shared__ __align__(16) char smem_raw[];
    const uint32_t sbase = (uint32_t)__cvta_generic_to_shared(smem_raw);
    const int tid  = threadIdx.x;
    const int lane = tid & 31;
    const int warp = tid >> 5;
    const int wm   = warp >> 1;          // 0..3 -> m offset wm*32
    const int wn   = warp & 1;           // 0..1 -> n offset wn*64
    const int bm   = blockIdx.y * 128;
    const int bn   = blockIdx.x * 128;

    const __nv_bfloat16* gp[4] = {
        Ahi + (size_t)bm * K, Alo + (size_t)bm * K,
        Bhi + (size_t)bn * K, Blo + (size_t)bn * K };

    float c[2][8][4];
#pragma unroll
    for (int i = 0; i < 2; i++)
#pragma unroll
        for (int j = 0; j < 8; j++)
#pragma unroll
            for (int q = 0; q < 4; q++) c[i][j][q] = 0.0f;

    const int row_l = tid >> 2;          // 0..63? no: tid/4 in 0..63 for idx<256
    // loader: 4 arrays, 2 iters of 256 threads -> 8 cp.async of 16B per thread
    auto load_stage = [&](int stg, int k0) {
        uint32_t sb = sbase + stg * GSTG;
#pragma unroll
        for (int arr = 0; arr < 4; arr++) {
#pragma unroll
            for (int it = 0; it < 2; it++) {
                int idx = tid + it * 256;       // 0..511
                int row = idx >> 2;             // 0..127
                int c4  = idx & 3;              // 16B chunk
                const void* g = gp[arr] + (size_t)row * K + k0 + c4 * 8;
                uint32_t s = sb + arr * GARR + row * 80 + c4 * 16;
                asm volatile("cp.async.cg.shared.global [%0], [%1], 16;" :: "r"(s), "l"(g));
            }
        }
        asm volatile("cp.async.commit_group;");
    };
    (void)row_l;

    load_stage(0, 0);
    const int KT = K >> 5;               // 64
    for (int kt = 0; kt < KT; kt++) {
        if (kt + 1 < KT) {
            load_stage((kt + 1) & 1, (kt + 1) * 32);
            asm volatile("cp.async.wait_group 1;");
        } else {
            asm volatile("cp.async.wait_group 0;");
        }
        __syncthreads();

        uint32_t sb = sbase + (kt & 1) * GSTG;
#pragma unroll
        for (int s16 = 0; s16 < 2; s16++) {
            const int ko = s16 * 16;     // halves
            uint32_t a_hi[2][4], a_lo[2][4], b_hi[4][4], b_lo[4][4];
#pragma unroll
            for (int i = 0; i < 2; i++) {
                uint32_t ar = sb + (wm * 32 + i * 16 + (lane & 15)) * 80
                                 + (ko + (lane >> 4) * 8) * 2;
                ldm_x4(a_hi[i], ar);
                ldm_x4(a_lo[i], ar + GARR);
            }
            const int grp = lane >> 3, rr = lane & 7;
#pragma unroll
            for (int jp = 0; jp < 4; jp++) {
                int row = wn * 64 + jp * 16 + (grp >> 1) * 8 + rr;
                uint32_t br = sb + 2 * GARR + row * 80 + (ko + (grp & 1) * 8) * 2;
                ldm_x4(b_hi[jp], br);
                ldm_x4(b_lo[jp], br + GARR);
            }
#pragma unroll
            for (int i = 0; i < 2; i++)
#pragma unroll
                for (int j = 0; j < 8; j++) {
                    const int jp = j >> 1, off = (j & 1) * 2;
                    mma16816(c[i][j], a_hi[i], &b_hi[jp][off]);
                    mma16816(c[i][j], a_hi[i], &b_lo[jp][off]);
                    mma16816(c[i][j], a_lo[i], &b_hi[jp][off]);
                }
        }
        __syncthreads();
    }

    // epilogue
    const int rowb = bm + wm * 32 + (lane >> 2);
    const int colb = bn + wn * 64 + (lane & 3) * 2;
#pragma unroll
    for (int i = 0; i < 2; i++)
#pragma unroll
        for (int j = 0; j < 8; j++) {
            int row = rowb + i * 16;
            int col = colb + j * 8;
            *(float2*)&C[(size_t)row * N + col]       = make_float2(c[i][j][0], c[i][j][1]);
            *(float2*)&C[(size_t)(row + 8) * N + col] = make_float2(c[i][j][2], c[i][j][3]);
        }
}

// ---------------------------------------------------------------------------
// RoPE (unchanged)
// ---------------------------------------------------------------------------
__global__ void rope_kernel(float* __restrict__ t,
                            const float* __restrict__ fc,
                            const float* __restrict__ fs, int nh)
{
    int idx = blockIdx.x * blockDim.x + threadIdx.x;
    int total = B_ * L_ * nh * (D_ / 2);
    if (idx >= total) return;
    int p = idx & 31;
    int rest = idx >> 5;
    int h = rest % nh;
    rest /= nh;
    int l = rest % L_;
    int b = rest / L_;
    float c = fc[l * 32 + p];
    float s = fs[l * 32 + p];
    float2* base = (float2*)t + ((size_t)((b * L_ + l) * nh + h) * 32 + p);
    float2 v = *base;
    *base = make_float2(v.x * c - v.y * s, v.x * s + v.y * c);
}

// ---------------------------------------------------------------------------
// Causal GQA flash attention (fp32, online softmax) — unchanged this round.
// ---------------------------------------------------------------------------
#define ATT_STRIDE 68
#define SM_QS 0
#define SM_KS (64 * ATT_STRIDE)
#define SM_VS (2 * 64 * ATT_STRIDE)
#define SM_PT (3 * 64 * ATT_STRIDE)
#define SM_MS (4 * 64 * ATT_STRIDE)
#define SM_LS (4 * 64 * ATT_STRIDE + 64)
#define ATT_SMEM_FLOATS (4 * 64 * ATT_STRIDE + 128)
#define ATT_SMEM_BYTES (ATT_SMEM_FLOATS * 4)

__global__ __launch_bounds__(256) void attn_kernel()
{
    extern __shared__ float sm[];
    const int qb  = blockIdx.x;
    const int h   = blockIdx.y;
    const int b   = blockIdx.z;
    const int kvh = h >> 2;
    const int tid = threadIdx.x;
    const int tx  = tid & 15;
    const int ty  = tid >> 4;
    const int r0  = ty * 4;
    const int c0  = tx * 4;

    {
        const float* qg = g_q + ((size_t)(b * L_ + qb * 64) * H_ + h) * D_;
#pragma unroll
        for (int i = 0; i < 4; i++) {
            int f   = tid + i * 256;
            int row = f >> 4;
            int dd  = (f & 15) << 2;
            float4 v = *(const float4*)(qg + (size_t)row * (H_ * D_) + dd);
            sm[SM_QS + (dd + 0) * ATT_STRIDE + row] = v.x * 0.125f;
            sm[SM_QS + (dd + 1) * ATT_STRIDE + row] = v.y * 0.125f;
            sm[SM_QS + (dd + 2) * ATT_STRIDE + row] = v.z * 0.125f;
            sm[SM_QS + (dd + 3) * ATT_STRIDE + row] = v.w * 0.125f;
        }
        if (tid < 64) {
            sm[SM_MS + tid] = -1e30f;
            sm[SM_LS + tid] = 0.0f;
        }
    }
    __syncthreads();

    float O[4][4];
#pragma unroll
    for (int i = 0; i < 4; i++)
#pragma unroll
        for (int j = 0; j < 4; j++) O[i][j] = 0.0f;

    for (int kb = 0; kb <= qb; kb++) {
        const float* kg = g_k + ((size_t)(b * L_ + kb * 64) * KVH_ + kvh) * D_;
        const float* vg = g_v + ((size_t)(b * L_ + kb * 64) * KVH_ + kvh) * D_;
#pragma unroll
        for (int i = 0; i < 4; i++) {
            int f   = tid + i * 256;
            int row = f >> 4;
            int dd  = (f & 15) << 2;
            float4 kv = *(const float4*)(kg + (size_t)row * (KVH_ * D_) + dd);
            sm[SM_KS + (dd + 0) * ATT_STRIDE + row] = kv.x;
            sm[SM_KS + (dd + 1) * ATT_STRIDE + row] = kv.y;
            sm[SM_KS + (dd + 2) * ATT_STRIDE + row] = kv.z;
            sm[SM_KS + (dd + 3) * ATT_STRIDE + row] = kv.w;
            float4 vv = *(const float4*)(vg + (size_t)row * (KVH_ * D_) + dd);
            *(float4*)(sm + SM_VS + row * ATT_STRIDE + dd) = vv;
        }
        __syncthreads();

        float s[4][4];
#pragma unroll
        for (int i = 0; i < 4; i++)
#pragma unroll
            for (int j = 0; j < 4; j++) s[i][j] = 0.0f;

#pragma unroll 8
        for (int d = 0; d < 64; d++) {
            float4 a4 = *(const float4*)(sm + SM_QS + d * ATT_STRIDE + r0);
            float4 k4 = *(const float4*)(sm + SM_KS + d * ATT_STRIDE + c0);
            float av[4] = {a4.x, a4.y, a4.z, a4.w};
            float kv[4] = {k4.x, k4.y, k4.z, k4.w};
#pragma unroll
            for (int i = 0; i < 4; i++)
#pragma unroll
                for (int j = 0; j < 4; j++)
                    s[i][j] = fmaf(av[i], kv[j], s[i][j]);
        }

        if (kb == qb) {
#pragma unroll
            for (int i = 0; i < 4; i++)
#pragma unroll
                for (int j = 0; j < 4; j++)
                    if (c0 + j > r0 + i) s[i][j] = -1e30f;
        }

        float alpha[4];
#pragma unroll
        for (int i = 0; i < 4; i++) {
            float mx = fmaxf(fmaxf(s[i][0], s[i][1]), fmaxf(s[i][2], s[i][3]));
#pragma unroll
            for (int off = 8; off > 0; off >>= 1)
                mx = fmaxf(mx, __shfl_xor_sync(0xffffffffu, mx, off, 16));
            float mold = sm[SM_MS + r0 + i];
            float mnew = fmaxf(mold, mx);
            alpha[i] = __expf(mold - mnew);
            float sum = 0.0f;
#pragma unroll
            for (int j = 0; j < 4; j++) {
                float p = __expf(s[i][j] - mnew);
                s[i][j] = p;
                sum += p;
            }
#pragma unroll
            for (int off = 8; off > 0; off >>= 1)
                sum += __shfl_xor_sync(0xffffffffu, sum, off, 16);
            __syncwarp();
            if (tx == 0) {
                sm[SM_MS + r0 + i] = mnew;
                sm[SM_LS + r0 + i] = sm[SM_LS + r0 + i] * alpha[i] + sum;
            }
#pragma unroll
            for (int j = 0; j < 4; j++)
                sm[SM_PT + (c0 + j) * ATT_STRIDE + (r0 + i)] = s[i][j];
        }
        __syncthreads();

#pragma unroll
        for (int i = 0; i < 4; i++)
#pragma unroll
            for (int j = 0; j < 4; j++) O[i][j] *= alpha[i];

#pragma unroll 8
        for (int kk = 0; kk < 64; kk++) {
            float4 p4 = *(const float4*)(sm + SM_PT + kk * ATT_STRIDE + r0);
            float4 v4 = *(const float4*)(sm + SM_VS + kk * ATT_STRIDE + c0);
            float pv[4] = {p4.x, p4.y, p4.z, p4.w};
            float vv[4] = {v4.x, v4.y, v4.z, v4.w};
#pragma unroll
            for (int i = 0; i < 4; i++)
#pragma unroll
                for (int j = 0; j < 4; j++)
                    O[i][j] = fmaf(pv[i], vv[j], O[i][j]);
        }
        __syncthreads();
    }

    float* og = g_att + ((size_t)(b * L_ + qb * 64) * H_ + h) * D_;
#pragma unroll
    for (int i = 0; i < 4; i++) {
        float inv = 1.0f / sm[SM_LS + r0 + i];
        float4 r = make_float4(O[i][0] * inv, O[i][1] * inv,
                               O[i][2] * inv, O[i][3] * inv);
        *(float4*)(og + (size_t)(r0 + i) * (H_ * D_) + c0) = r;
    }
}

// ---------------------------------------------------------------------------
// Launch
// ---------------------------------------------------------------------------
static inline void run_split(const float* src, __nv_bfloat16* hi, __nv_bfloat16* lo, size_t n)
{
    int n4 = (int)(n / 4);
    split_kernel<<<(n4 + 255) / 256, 256>>>(src, hi, lo, n4);
}

extern "C" void kernel_launch(void* const* d_in, const int* in_sizes, int n_in,
                              void* d_out, int out_size)
{
    const float* x  = (const float*)d_in[0];
    const float* wq = (const float*)d_in[1];
    const float* wk = (const float*)d_in[2];
    const float* wv = (const float*)d_in[3];
    const float* wo = (const float*)d_in[4];
    const float* fc = (const float*)d_in[5];
    const float* fs = (const float*)d_in[6];
    float* out = (float*)d_out;

    float *gq, *gk, *gv, *ga;
    cudaGetSymbolAddress((void**)&gq, g_q);
    cudaGetSymbolAddress((void**)&gk, g_k);
    cudaGetSymbolAddress((void**)&gv, g_v);
    cudaGetSymbolAddress((void**)&ga, g_att);

    __nv_bfloat16 *xhi, *xlo, *wqhi, *wqlo, *wkhi, *wklo, *wvhi, *wvlo, *wohi, *wolo, *ahi, *alo;
    cudaGetSymbolAddress((void**)&xhi,  g_xhi);  cudaGetSymbolAddress((void**)&xlo,  g_xlo);
    cudaGetSymbolAddress((void**)&wqhi, g_wqhi); cudaGetSymbolAddress((void**)&wqlo, g_wqlo);
    cudaGetSymbolAddress((void**)&wkhi, g_wkhi); cudaGetSymbolAddress((void**)&wklo, g_wklo);
    cudaGetSymbolAddress((void**)&wvhi, g_wvhi); cudaGetSymbolAddress((void**)&wvlo, g_wvlo);
    cudaGetSymbolAddress((void**)&wohi, g_wohi); cudaGetSymbolAddress((void**)&wolo, g_wolo);
    cudaGetSymbolAddress((void**)&ahi,  g_ahi);  cudaGetSymbolAddress((void**)&alo,  g_alo);

    const int M = B_ * L_;                       // 4096

    cudaFuncSetAttribute(gemm_bf16x3, cudaFuncAttributeMaxDynamicSharedMemorySize, GEMM_SMEM);

    // Split inputs to bf16 hi/lo
    run_split(x,  xhi,  xlo,  NX);
    run_split(wq, wqhi, wqlo, NWQ);
    run_split(wk, wkhi, wklo, NWK);
    run_split(wv, wvhi, wvlo, NWK);
    run_split(wo, wohi, wolo, NWO);

    // QKV projections (tensor cores, bf16x3)
    gemm_bf16x3<<<dim3((H_ * D_) / 128,   M / 128), 256, GEMM_SMEM>>>(xhi, xlo, wqhi, wqlo, gq, M, H_ * D_,   HID_);
    gemm_bf16x3<<<dim3((KVH_ * D_) / 128, M / 128), 256, GEMM_SMEM>>>(xhi, xlo, wkhi, wklo, gk, M, KVH_ * D_, HID_);
    gemm_bf16x3<<<dim3((KVH_ * D_) / 128, M / 128), 256, GEMM_SMEM>>>(xhi, xlo, wvhi, wvlo, gv, M, KVH_ * D_, HID_);

    // RoPE
    {
        int nq = B_ * L_ * H_ * (D_ / 2);
        int nk = B_ * L_ * KVH_ * (D_ / 2);
        rope_kernel<<<(nq + 255) / 256, 256>>>(gq, fc, fs, H_);
        rope_kernel<<<(nk + 255) / 256, 256>>>(gk, fc, fs, KVH_);
    }

    // Attention (fp32)
    cudaFuncSetAttribute(attn_kernel, cudaFuncAttributeMaxDynamicSharedMemorySize, ATT_SMEM_BYTES);
    attn_kernel<<<dim3(L_ / 64, H_, B_), 256, ATT_SMEM_BYTES>>>();

    // Output projection
    run_split(ga, ahi, alo, NX);
    gemm_bf16x3<<<dim3(HID_ / 128, M / 128), 256, GEMM_SMEM>>>(ahi, alo, wohi, wolo, out, M, HID_, H_ * D_);
}

// round 4
// speedup vs baseline: 2.6307x; 1.6678x over previous
#include <cuda_runtime.h>
#include <cuda_bf16.h>
#include <cstdint>

// Problem constants
#define B_   2
#define L_   2048
#define HID_ 2048
#define H_   32
#define KVH_ 8
#define D_   64

// ---------------------------------------------------------------------------
// Scratch (static device arrays; no allocation allowed)
// ---------------------------------------------------------------------------
__device__ float g_q  [(size_t)B_ * L_ * H_   * D_];
__device__ float g_k  [(size_t)B_ * L_ * KVH_ * D_];
__device__ float g_v  [(size_t)B_ * L_ * KVH_ * D_];

#define NX  ((size_t)B_ * L_ * HID_)
#define NQ  ((size_t)B_ * L_ * H_ * D_)
#define NKV ((size_t)B_ * L_ * KVH_ * D_)
#define NWQ ((size_t)H_ * D_ * HID_)
#define NWK ((size_t)KVH_ * D_ * HID_)
#define NWO ((size_t)HID_ * H_ * D_)
__device__ __nv_bfloat16 g_xhi [NX],  g_xlo [NX];
__device__ __nv_bfloat16 g_wqhi[NWQ], g_wqlo[NWQ];
__device__ __nv_bfloat16 g_wkhi[NWK], g_wklo[NWK];
__device__ __nv_bfloat16 g_wvhi[NWK], g_wvlo[NWK];
__device__ __nv_bfloat16 g_wohi[NWO], g_wolo[NWO];
__device__ __nv_bfloat16 g_ahi [NX],  g_alo [NX];
__device__ __nv_bfloat16 g_qhi [NQ],  g_qlo [NQ];
__device__ __nv_bfloat16 g_khi [NKV], g_klo [NKV];
__device__ __nv_bfloat16 g_vhi [NKV], g_vlo [NKV];

// ---------------------------------------------------------------------------
// Common PTX helpers
// ---------------------------------------------------------------------------
__device__ __forceinline__ void ldm_x4(uint32_t* r, uint32_t addr) {
    asm volatile("ldmatrix.sync.aligned.m8n8.x4.shared.b16 {%0,%1,%2,%3}, [%4];"
                 : "=r"(r[0]), "=r"(r[1]), "=r"(r[2]), "=r"(r[3]) : "r"(addr));
}
__device__ __forceinline__ void ldm_x4_t(uint32_t* r, uint32_t addr) {
    asm volatile("ldmatrix.sync.aligned.m8n8.x4.trans.shared.b16 {%0,%1,%2,%3}, [%4];"
                 : "=r"(r[0]), "=r"(r[1]), "=r"(r[2]), "=r"(r[3]) : "r"(addr));
}
__device__ __forceinline__ void mma16816(float* d, const uint32_t* a, const uint32_t* b) {
    asm volatile("mma.sync.aligned.m16n8k16.row.col.f32.bf16.bf16.f32 "
                 "{%0,%1,%2,%3}, {%4,%5,%6,%7}, {%8,%9}, {%0,%1,%2,%3};"
                 : "+f"(d[0]), "+f"(d[1]), "+f"(d[2]), "+f"(d[3])
                 : "r"(a[0]), "r"(a[1]), "r"(a[2]), "r"(a[3]), "r"(b[0]), "r"(b[1]));
}
#define CP_ASYNC16(dst, src) \
    asm volatile("cp.async.cg.shared.global [%0], [%1], 16;" :: "r"(dst), "l"(src))

// ---------------------------------------------------------------------------
// Split fp32 -> bf16 hi + bf16 lo
// ---------------------------------------------------------------------------
__global__ void split_kernel(const float* __restrict__ in,
                             __nv_bfloat16* __restrict__ hi,
                             __nv_bfloat16* __restrict__ lo, int n4)
{
    int i = blockIdx.x * blockDim.x + threadIdx.x;
    if (i >= n4) return;
    float4 v = ((const float4*)in)[i];
    __nv_bfloat16 h0 = __float2bfloat16(v.x);
    __nv_bfloat16 h1 = __float2bfloat16(v.y);
    __nv_bfloat16 h2 = __float2bfloat16(v.z);
    __nv_bfloat16 h3 = __float2bfloat16(v.w);
    __nv_bfloat16 l0 = __float2bfloat16(v.x - __bfloat162float(h0));
    __nv_bfloat16 l1 = __float2bfloat16(v.y - __bfloat162float(h1));
    __nv_bfloat16 l2 = __float2bfloat16(v.z - __bfloat162float(h2));
    __nv_bfloat16 l3 = __float2bfloat16(v.w - __bfloat162float(h3));
    ((__nv_bfloat162*)hi)[2 * i + 0] = __halves2bfloat162(h0, h1);
    ((__nv_bfloat162*)hi)[2 * i + 1] = __halves2bfloat162(h2, h3);
    ((__nv_bfloat162*)lo)[2 * i + 0] = __halves2bfloat162(l0, l1);
    ((__nv_bfloat162*)lo)[2 * i + 1] = __halves2bfloat162(l2, l3);
}

// ---------------------------------------------------------------------------
// RoPE + scale + split: fp32 [B,L,nh,D] -> rotated*scale as bf16 hi/lo
// ---------------------------------------------------------------------------
__global__ void rope_split_kernel(const float* __restrict__ src,
                                  __nv_bfloat16* __restrict__ hi,
                                  __nv_bfloat16* __restrict__ lo,
                                  const float* __restrict__ fc,
                                  const float* __restrict__ fs,
                                  int nh, float scale)
{
    int idx = blockIdx.x * blockDim.x + threadIdx.x;
    int total = B_ * L_ * nh * (D_ / 2);
    if (idx >= total) return;
    int p = idx & 31;
    int rest = idx >> 5;
    int h = rest % nh;
    rest /= nh;
    int l = rest % L_;
    int b = rest / L_;
    float c = fc[l * 32 + p];
    float s = fs[l * 32 + p];
    size_t off = (size_t)((b * L_ + l) * nh + h) * 32 + p;   // float2 units
    float2 v = ((const float2*)src)[off];
    float o1 = (v.x * c - v.y * s) * scale;
    float o2 = (v.x * s + v.y * c) * scale;
    __nv_bfloat16 h1 = __float2bfloat16(o1);
    __nv_bfloat16 h2 = __float2bfloat16(o2);
    ((__nv_bfloat162*)hi)[off] = __halves2bfloat162(h1, h2);
    ((__nv_bfloat162*)lo)[off] = __halves2bfloat162(
        __float2bfloat16(o1 - __bfloat162float(h1)),
        __float2bfloat16(o2 - __bfloat162float(h2)));
}

// ---------------------------------------------------------------------------
// Tensor-core NT GEMM, bf16x3 (unchanged from round 3 — verified correct)
// ---------------------------------------------------------------------------
#define GSTG 40960
#define GARR 10240
#define GEMM_SMEM (2 * GSTG)

__global__ __launch_bounds__(256) void gemm_bf16x3(
    const __nv_bfloat16* __restrict__ Ahi, const __nv_bfloat16* __restrict__ Alo,
    const __nv_bfloat16* __restrict__ Bhi, const __nv_bfloat16* __restrict__ Blo,
    float* __restrict__ C, int M, int N, int K)
{
    extern __shared__ __align__(16) char smem_raw[];
    const uint32_t sbase = (uint32_t)__cvta_generic_to_shared(smem_raw);
    const int tid  = threadIdx.x;
    const int lane = tid & 31;
    const int warp = tid >> 5;
    const int wm   = warp >> 1;
    const int wn   = warp & 1;
    const int bm   = blockIdx.y * 128;
    const int bn   = blockIdx.x * 128;

    const __nv_bfloat16* gp[4] = {
        Ahi + (size_t)bm * K, Alo + (size_t)bm * K,
        Bhi + (size_t)bn * K, Blo + (size_t)bn * K };

    float c[2][8][4];
#pragma unroll
    for (int i = 0; i < 2; i++)
#pragma unroll
        for (int j = 0; j < 8; j++)
#pragma unroll
            for (int q = 0; q < 4; q++) c[i][j][q] = 0.0f;

    auto load_stage = [&](int stg, int k0) {
        uint32_t sb = sbase + stg * GSTG;
#pragma unroll
        for (int arr = 0; arr < 4; arr++) {
#pragma unroll
            for (int it = 0; it < 2; it++) {
                int idx = tid + it * 256;
                int row = idx >> 2;
                int c4  = idx & 3;
                const void* g = gp[arr] + (size_t)row * K + k0 + c4 * 8;
                uint32_t s = sb + arr * GARR + row * 80 + c4 * 16;
                CP_ASYNC16(s, g);
            }
        }
        asm volatile("cp.async.commit_group;");
    };

    load_stage(0, 0);
    const int KT = K >> 5;
    for (int kt = 0; kt < KT; kt++) {
        if (kt + 1 < KT) {
            load_stage((kt + 1) & 1, (kt + 1) * 32);
            asm volatile("cp.async.wait_group 1;");
        } else {
            asm volatile("cp.async.wait_group 0;");
        }
        __syncthreads();

        uint32_t sb = sbase + (kt & 1) * GSTG;
#pragma unroll
        for (int s16 = 0; s16 < 2; s16++) {
            const int ko = s16 * 16;
            uint32_t a_hi[2][4], a_lo[2][4], b_hi[4][4], b_lo[4][4];
#pragma unroll
            for (int i = 0; i < 2; i++) {
                uint32_t ar = sb + (wm * 32 + i * 16 + (lane & 15)) * 80
                                 + (ko + (lane >> 4) * 8) * 2;
                ldm_x4(a_hi[i], ar);
                ldm_x4(a_lo[i], ar + GARR);
            }
            const int grp = lane >> 3, rr = lane & 7;
#pragma unroll
            for (int jp = 0; jp < 4; jp++) {
                int row = wn * 64 + jp * 16 + (grp >> 1) * 8 + rr;
                uint32_t br = sb + 2 * GARR + row * 80 + (ko + (grp & 1) * 8) * 2;
                ldm_x4(b_hi[jp], br);
                ldm_x4(b_lo[jp], br + GARR);
            }
#pragma unroll
            for (int i = 0; i < 2; i++)
#pragma unroll
                for (int j = 0; j < 8; j++) {
                    const int jp = j >> 1, off = (j & 1) * 2;
                    mma16816(c[i][j], a_hi[i], &b_hi[jp][off]);
                    mma16816(c[i][j], a_hi[i], &b_lo[jp][off]);
                    mma16816(c[i][j], a_lo[i], &b_hi[jp][off]);
                }
        }
        __syncthreads();
    }

    const int rowb = bm + wm * 32 + (lane >> 2);
    const int colb = bn + wn * 64 + (lane & 3) * 2;
#pragma unroll
    for (int i = 0; i < 2; i++)
#pragma unroll
        for (int j = 0; j < 8; j++) {
            int row = rowb + i * 16;
            int col = colb + j * 8;
            *(float2*)&C[(size_t)row * N + col]       = make_float2(c[i][j][0], c[i][j][1]);
            *(float2*)&C[(size_t)(row + 8) * N + col] = make_float2(c[i][j][2], c[i][j][3]);
        }
}

// ---------------------------------------------------------------------------
// Tensor-core causal GQA flash attention, bf16x3.
// CTA = (64 queries, head, batch); 4 warps x 16 query rows.
// smem rows padded to 72 halves (144B): conflict-free for ldmatrix (+trans).
// Layout (halves): Qhi 0, Qlo 4608, then 2 stages of {Khi,Klo,Vhi,Vlo} x 4608.
// ---------------------------------------------------------------------------
#define SROW 72
#define STG_HALVES 18432
#define ATTN_SMEM_BYTES ((9216 + 2 * STG_HALVES) * 2)   // 92160

__global__ __launch_bounds__(128) void attn_mma(
    const __nv_bfloat16* __restrict__ Qhi, const __nv_bfloat16* __restrict__ Qlo,
    const __nv_bfloat16* __restrict__ Khi, const __nv_bfloat16* __restrict__ Klo,
    const __nv_bfloat16* __restrict__ Vhi, const __nv_bfloat16* __restrict__ Vlo,
    __nv_bfloat16* __restrict__ Ohi, __nv_bfloat16* __restrict__ Olo)
{
    extern __shared__ __align__(16) char smem_raw[];
    const uint32_t sb = (uint32_t)__cvta_generic_to_shared(smem_raw);
    const int qb  = (int)(gridDim.x - 1 - blockIdx.x);   // heavy blocks first
    const int h   = blockIdx.y;
    const int b   = blockIdx.z;
    const int kvh = h >> 2;
    const int tid  = threadIdx.x;
    const int lane = tid & 31;
    const int warp = tid >> 5;

    // ---- async load Q (hi+lo), transposed-free row layout ----
    {
        const size_t qoff = ((size_t)(b * L_ + qb * 64) * H_ + h) * D_;
        const __nv_bfloat16* qs[2] = { Qhi + qoff, Qlo + qoff };
#pragma unroll
        for (int arr = 0; arr < 2; arr++)
#pragma unroll
            for (int it = 0; it < 4; it++) {
                int idx = tid + it * 128, row = idx >> 3, ch = idx & 7;
                uint32_t dst = sb + (arr * 4608 + row * SROW + ch * 8) * 2;
                const void* src = qs[arr] + (size_t)row * (H_ * D_) + ch * 8;
                CP_ASYNC16(dst, src);
            }
    }
    auto load_kv = [&](int stg, int kb) {
        const size_t koff = ((size_t)(b * L_ + kb * 64) * KVH_ + kvh) * D_;
        const __nv_bfloat16* srcs[4] = { Khi + koff, Klo + koff, Vhi + koff, Vlo + koff };
        uint32_t base = sb + (9216 + stg * STG_HALVES) * 2;
#pragma unroll
        for (int arr = 0; arr < 4; arr++)
#pragma unroll
            for (int it = 0; it < 4; it++) {
                int idx = tid + it * 128, row = idx >> 3, ch = idx & 7;
                uint32_t dst = base + (arr * 4608 + row * SROW + ch * 8) * 2;
                const void* src = srcs[arr] + (size_t)row * (KVH_ * D_) + ch * 8;
                CP_ASYNC16(dst, src);
            }
    };
    load_kv(0, 0);
    asm volatile("cp.async.commit_group;");

    float O[8][4];
#pragma unroll
    for (int nt = 0; nt < 8; nt++)
#pragma unroll
        for (int q = 0; q < 4; q++) O[nt][q] = 0.0f;
    float m0 = -1e30f, m1 = -1e30f, l0 = 0.0f, l1 = 0.0f;

    const int grp = lane >> 3;

    for (int kb = 0; kb <= qb; kb++) {
        if (kb < qb) {
            load_kv((kb + 1) & 1, kb + 1);
            asm volatile("cp.async.commit_group;");
            asm volatile("cp.async.wait_group 1;");
        } else {
            asm volatile("cp.async.wait_group 0;");
        }
        __syncthreads();

        const uint32_t stb = sb + (9216 + (kb & 1) * STG_HALVES) * 2;

        // ---- S = Qhi*Khi + Qhi*Klo + Qlo*Khi ----
        float sc[8][4];
#pragma unroll
        for (int nt = 0; nt < 8; nt++)
#pragma unroll
            for (int q = 0; q < 4; q++) sc[nt][q] = 0.0f;

#pragma unroll
        for (int ks = 0; ks < 4; ks++) {
            uint32_t ah[4], al[4];
            uint32_t qa = sb + ((warp * 16 + (lane & 15)) * SROW
                                + ks * 16 + (lane >> 4) * 8) * 2;
            ldm_x4(ah, qa);
            ldm_x4(al, qa + 9216);
#pragma unroll
            for (int jn = 0; jn < 4; jn++) {
                uint32_t ka = stb + ((jn * 16 + (grp >> 1) * 8 + (lane & 7)) * SROW
                                     + ks * 16 + (grp & 1) * 8) * 2;
                uint32_t bh[4], bl[4];
                ldm_x4(bh, ka);
                ldm_x4(bl, ka + 9216);
                mma16816(sc[2 * jn],     ah, &bh[0]);
                mma16816(sc[2 * jn],     ah, &bl[0]);
                mma16816(sc[2 * jn],     al, &bh[0]);
                mma16816(sc[2 * jn + 1], ah, &bh[2]);
                mma16816(sc[2 * jn + 1], ah, &bl[2]);
                mma16816(sc[2 * jn + 1], al, &bh[2]);
            }
        }

        // ---- causal mask on diagonal block ----
        const int r0g = qb * 64 + warp * 16 + (lane >> 2);
        if (kb == qb) {
            const int cb = kb * 64 + (lane & 3) * 2;
#pragma unroll
            for (int nt = 0; nt < 8; nt++) {
                int c = cb + nt * 8;
                if (c     > r0g)     sc[nt][0] = -1e30f;
                if (c + 1 > r0g)     sc[nt][1] = -1e30f;
                if (c     > r0g + 8) sc[nt][2] = -1e30f;
                if (c + 1 > r0g + 8) sc[nt][3] = -1e30f;
            }
        }

        // ---- online softmax (rows live in lane quads) ----
        float mx0 = sc[0][0], mx1 = sc[0][2];
#pragma unroll
        for (int nt = 0; nt < 8; nt++) {
            mx0 = fmaxf(mx0, fmaxf(sc[nt][0], sc[nt][1]));
            mx1 = fmaxf(mx1, fmaxf(sc[nt][2], sc[nt][3]));
        }
        mx0 = fmaxf(mx0, __shfl_xor_sync(0xffffffffu, mx0, 1));
        mx0 = fmaxf(mx0, __shfl_xor_sync(0xffffffffu, mx0, 2));
        mx1 = fmaxf(mx1, __shfl_xor_sync(0xffffffffu, mx1, 1));
        mx1 = fmaxf(mx1, __shfl_xor_sync(0xffffffffu, mx1, 2));
        float mn0 = fmaxf(m0, mx0), mn1 = fmaxf(m1, mx1);
        float a0 = __expf(m0 - mn0), a1 = __expf(m1 - mn1);
        m0 = mn0; m1 = mn1;
        float s0 = 0.0f, s1 = 0.0f;
#pragma unroll
        for (int nt = 0; nt < 8; nt++) {
            sc[nt][0] = __expf(sc[nt][0] - mn0);
            sc[nt][1] = __expf(sc[nt][1] - mn0);
            sc[nt][2] = __expf(sc[nt][2] - mn1);
            sc[nt][3] = __expf(sc[nt][3] - mn1);
            s0 += sc[nt][0] + sc[nt][1];
            s1 += sc[nt][2] + sc[nt][3];
        }
        s0 += __shfl_xor_sync(0xffffffffu, s0, 1);
        s0 += __shfl_xor_sync(0xffffffffu, s0, 2);
        s1 += __shfl_xor_sync(0xffffffffu, s1, 1);
        s1 += __shfl_xor_sync(0xffffffffu, s1, 2);
        l0 = l0 * a0 + s0;
        l1 = l1 * a1 + s1;
#pragma unroll
        for (int nt = 0; nt < 8; nt++) {
            O[nt][0] *= a0; O[nt][1] *= a0;
            O[nt][2] *= a1; O[nt][3] *= a1;
        }

        // ---- O += Phi*Vhi + Phi*Vlo + Plo*Vhi (P packed from registers) ----
#pragma unroll
        for (int ks = 0; ks < 4; ks++) {
            uint32_t ph[4], pl[4];
#pragma unroll
            for (int t = 0; t < 2; t++) {
                int nt = 2 * ks + t;
#pragma unroll
                for (int j = 0; j < 2; j++) {
                    float x0 = sc[nt][2 * j], x1 = sc[nt][2 * j + 1];
                    __nv_bfloat16 h0 = __float2bfloat16(x0);
                    __nv_bfloat16 h1 = __float2bfloat16(x1);
                    __nv_bfloat162 hp = __halves2bfloat162(h0, h1);
                    __nv_bfloat162 lp = __halves2bfloat162(
                        __float2bfloat16(x0 - __bfloat162float(h0)),
                        __float2bfloat16(x1 - __bfloat162float(h1)));
                    ph[t * 2 + j] = *(uint32_t*)&hp;
                    pl[t * 2 + j] = *(uint32_t*)&lp;
                }
            }
#pragma unroll
            for (int dj = 0; dj < 4; dj++) {
                uint32_t va = stb + 18432
                            + ((ks * 16 + (grp & 1) * 8 + (lane & 7)) * SROW
                               + dj * 16 + (grp >> 1) * 8) * 2;
                uint32_t vh[4], vl[4];
                ldm_x4_t(vh, va);
                ldm_x4_t(vl, va + 9216);
                mma16816(O[2 * dj],     ph, &vh[0]);
                mma16816(O[2 * dj],     ph, &vl[0]);
                mma16816(O[2 * dj],     pl, &vh[0]);
                mma16816(O[2 * dj + 1], ph, &vh[2]);
                mma16816(O[2 * dj + 1], ph, &vl[2]);
                mma16816(O[2 * dj + 1], pl, &vh[2]);
            }
        }
        __syncthreads();
    }

    // ---- epilogue: normalize, split to bf16 hi/lo, store ----
    float i0 = 1.0f / l0, i1 = 1.0f / l1;
    const size_t ro = ((size_t)(b * L_ + qb * 64 + warp * 16 + (lane >> 2)) * H_ + h) * D_
                      + (lane & 3) * 2;
    const size_t r8 = ro + (size_t)8 * H_ * D_;
#pragma unroll
    for (int nt = 0; nt < 8; nt++) {
        float v0 = O[nt][0] * i0, v1 = O[nt][1] * i0;
        __nv_bfloat16 h0 = __float2bfloat16(v0), h1 = __float2bfloat16(v1);
        *(__nv_bfloat162*)(Ohi + ro + nt * 8) = __halves2bfloat162(h0, h1);
        *(__nv_bfloat162*)(Olo + ro + nt * 8) = __halves2bfloat162(
            __float2bfloat16(v0 - __bfloat162float(h0)),
            __float2bfloat16(v1 - __bfloat162float(h1)));
        float w0 = O[nt][2] * i1, w1 = O[nt][3] * i1;
        __nv_bfloat16 g0 = __float2bfloat16(w0), g1 = __float2bfloat16(w1);
        *(__nv_bfloat162*)(Ohi + r8 + nt * 8) = __halves2bfloat162(g0, g1);
        *(__nv_bfloat162*)(Olo + r8 + nt * 8) = __halves2bfloat162(
            __float2bfloat16(w0 - __bfloat162float(g0)),
            __float2bfloat16(w1 - __bfloat162float(g1)));
    }
}

// ---------------------------------------------------------------------------
// Launch
// ---------------------------------------------------------------------------
static inline void run_split(const float* src, __nv_bfloat16* hi, __nv_bfloat16* lo, size_t n)
{
    int n4 = (int)(n / 4);
    split_kernel<<<(n4 + 255) / 256, 256>>>(src, hi, lo, n4);
}

extern "C" void kernel_launch(void* const* d_in, const int* in_sizes, int n_in,
                              void* d_out, int out_size)
{
    const float* x  = (const float*)d_in[0];
    const float* wq = (const float*)d_in[1];
    const float* wk = (const float*)d_in[2];
    const float* wv = (const float*)d_in[3];
    const float* wo = (const float*)d_in[4];
    const float* fc = (const float*)d_in[5];
    const float* fs = (const float*)d_in[6];
    float* out = (float*)d_out;

    float *gq, *gk, *gv;
    cudaGetSymbolAddress((void**)&gq, g_q);
    cudaGetSymbolAddress((void**)&gk, g_k);
    cudaGetSymbolAddress((void**)&gv, g_v);

    __nv_bfloat16 *xhi, *xlo, *wqhi, *wqlo, *wkhi, *wklo, *wvhi, *wvlo, *wohi, *wolo;
    __nv_bfloat16 *ahi, *alo, *qhi, *qlo, *khi, *klo, *vhi, *vlo;
    cudaGetSymbolAddress((void**)&xhi,  g_xhi);  cudaGetSymbolAddress((void**)&xlo,  g_xlo);
    cudaGetSymbolAddress((void**)&wqhi, g_wqhi); cudaGetSymbolAddress((void**)&wqlo, g_wqlo);
    cudaGetSymbolAddress((void**)&wkhi, g_wkhi); cudaGetSymbolAddress((void**)&wklo, g_wklo);
    cudaGetSymbolAddress((void**)&wvhi, g_wvhi); cudaGetSymbolAddress((void**)&wvlo, g_wvlo);
    cudaGetSymbolAddress((void**)&wohi, g_wohi); cudaGetSymbolAddress((void**)&wolo, g_wolo);
    cudaGetSymbolAddress((void**)&ahi,  g_ahi);  cudaGetSymbolAddress((void**)&alo,  g_alo);
    cudaGetSymbolAddress((void**)&qhi,  g_qhi);  cudaGetSymbolAddress((void**)&qlo,  g_qlo);
    cudaGetSymbolAddress((void**)&khi,  g_khi);  cudaGetSymbolAddress((void**)&klo,  g_klo);
    cudaGetSymbolAddress((void**)&vhi,  g_vhi);  cudaGetSymbolAddress((void**)&vlo,  g_vlo);

    const int M = B_ * L_;                       // 4096

    cudaFuncSetAttribute(gemm_bf16x3, cudaFuncAttributeMaxDynamicSharedMemorySize, GEMM_SMEM);
    cudaFuncSetAttribute(attn_mma, cudaFuncAttributeMaxDynamicSharedMemorySize, ATTN_SMEM_BYTES);

    // Split inputs to bf16 hi/lo
    run_split(x,  xhi,  xlo,  NX);
    run_split(wq, wqhi, wqlo, NWQ);
    run_split(wk, wkhi, wklo, NWK);
    run_split(wv, wvhi, wvlo, NWK);
    run_split(wo, wohi, wolo, NWO);

    // QKV projections (tensor cores, bf16x3)
    gemm_bf16x3<<<dim3((H_ * D_) / 128,   M / 128), 256, GEMM_SMEM>>>(xhi, xlo, wqhi, wqlo, gq, M, H_ * D_,   HID_);
    gemm_bf16x3<<<dim3((KVH_ * D_) / 128, M / 128), 256, GEMM_SMEM>>>(xhi, xlo, wkhi, wklo, gk, M, KVH_ * D_, HID_);
    gemm_bf16x3<<<dim3((KVH_ * D_) / 128, M / 128), 256, GEMM_SMEM>>>(xhi, xlo, wvhi, wvlo, gv, M, KVH_ * D_, HID_);

    // RoPE + split to bf16 hi/lo (Q gets the 1/sqrt(D) fold)
    {
        int nq = B_ * L_ * H_ * (D_ / 2);
        int nk = B_ * L_ * KVH_ * (D_ / 2);
        rope_split_kernel<<<(nq + 255) / 256, 256>>>(gq, qhi, qlo, fc, fs, H_, 0.125f);
        rope_split_kernel<<<(nk + 255) / 256, 256>>>(gk, khi, klo, fc, fs, KVH_, 1.0f);
    }
    run_split(gv, vhi, vlo, NKV);

    // Attention (tensor cores, bf16x3, writes hi/lo split directly)
    attn_mma<<<dim3(L_ / 64, H_, B_), 128, ATTN_SMEM_BYTES>>>(
        qhi, qlo, khi, klo, vhi, vlo, ahi, alo);

    // Output projection
    gemm_bf16x3<<<dim3(HID_ / 128, M / 128), 256, GEMM_SMEM>>>(ahi, alo, wohi, wolo, out, M, HID_, H_ * D_);
}

// round 5
// speedup vs baseline: 2.6621x; 1.0119x over previous
#include <cuda_runtime.h>
#include <cuda_bf16.h>
#include <cstdint>

// Problem constants
#define B_   2
#define L_   2048
#define HID_ 2048
#define H_   32
#define KVH_ 8
#define D_   64

#define NX  ((size_t)B_ * L_ * HID_)
#define NQ  ((size_t)B_ * L_ * H_ * D_)
#define NKV ((size_t)B_ * L_ * KVH_ * D_)
#define NWQ ((size_t)H_ * D_ * HID_)
#define NWK ((size_t)KVH_ * D_ * HID_)
#define NWO ((size_t)HID_ * H_ * D_)

__device__ __nv_bfloat16 g_xhi  [NX],      g_xlo  [NX];
__device__ __nv_bfloat16 g_wqhi [NWQ],     g_wqlo [NWQ];
__device__ __nv_bfloat16 g_wkvhi[2 * NWK], g_wkvlo[2 * NWK];   // wk rows then wv rows
__device__ __nv_bfloat16 g_wohi [NWO],     g_wolo [NWO];
__device__ __nv_bfloat16 g_ahi  [NX],      g_alo  [NX];
__device__ __nv_bfloat16 g_qhi  [NQ],      g_qlo  [NQ];
__device__ __nv_bfloat16 g_khi  [NKV],     g_klo  [NKV];
__device__ __nv_bfloat16 g_vhi  [NKV],     g_vlo  [NKV];

// ---------------------------------------------------------------------------
// PTX helpers
// ---------------------------------------------------------------------------
__device__ __forceinline__ void ldm_x4(uint32_t* r, uint32_t addr) {
    asm volatile("ldmatrix.sync.aligned.m8n8.x4.shared.b16 {%0,%1,%2,%3}, [%4];"
                 : "=r"(r[0]), "=r"(r[1]), "=r"(r[2]), "=r"(r[3]) : "r"(addr));
}
__device__ __forceinline__ void ldm_x4_t(uint32_t* r, uint32_t addr) {
    asm volatile("ldmatrix.sync.aligned.m8n8.x4.trans.shared.b16 {%0,%1,%2,%3}, [%4];"
                 : "=r"(r[0]), "=r"(r[1]), "=r"(r[2]), "=r"(r[3]) : "r"(addr));
}
__device__ __forceinline__ void mma16816(float* d, const uint32_t* a, const uint32_t* b) {
    asm volatile("mma.sync.aligned.m16n8k16.row.col.f32.bf16.bf16.f32 "
                 "{%0,%1,%2,%3}, {%4,%5,%6,%7}, {%8,%9}, {%0,%1,%2,%3};"
                 : "+f"(d[0]), "+f"(d[1]), "+f"(d[2]), "+f"(d[3])
                 : "r"(a[0]), "r"(a[1]), "r"(a[2]), "r"(a[3]), "r"(b[0]), "r"(b[1]));
}
#define CP_ASYNC16(dst, src) \
    asm volatile("cp.async.cg.shared.global [%0], [%1], 16;" :: "r"(dst), "l"(src))

__device__ __forceinline__ void split_store(__nv_bfloat16* hi, __nv_bfloat16* lo,
                                            size_t idx, float v0, float v1)
{
    __nv_bfloat16 h0 = __float2bfloat16(v0), h1 = __float2bfloat16(v1);
    *(__nv_bfloat162*)(hi + idx) = __halves2bfloat162(h0, h1);
    *(__nv_bfloat162*)(lo + idx) = __halves2bfloat162(
        __float2bfloat16(v0 - __bfloat162float(h0)),
        __float2bfloat16(v1 - __bfloat162float(h1)));
}

// ---------------------------------------------------------------------------
// Split fp32 -> bf16 hi + bf16 lo
// ---------------------------------------------------------------------------
__global__ void split_kernel(const float* __restrict__ in,
                             __nv_bfloat16* __restrict__ hi,
                             __nv_bfloat16* __restrict__ lo, int n4)
{
    int i = blockIdx.x * blockDim.x + threadIdx.x;
    if (i >= n4) return;
    float4 v = ((const float4*)in)[i];
    __nv_bfloat16 h0 = __float2bfloat16(v.x);
    __nv_bfloat16 h1 = __float2bfloat16(v.y);
    __nv_bfloat16 h2 = __float2bfloat16(v.z);
    __nv_bfloat16 h3 = __float2bfloat16(v.w);
    ((__nv_bfloat162*)hi)[2 * i + 0] = __halves2bfloat162(h0, h1);
    ((__nv_bfloat162*)hi)[2 * i + 1] = __halves2bfloat162(h2, h3);
    ((__nv_bfloat162*)lo)[2 * i + 0] = __halves2bfloat162(
        __float2bfloat16(v.x - __bfloat162float(h0)),
        __float2bfloat16(v.y - __bfloat162float(h1)));
    ((__nv_bfloat162*)lo)[2 * i + 1] = __halves2bfloat162(
        __float2bfloat16(v.z - __bfloat162float(h2)),
        __float2bfloat16(v.w - __bfloat162float(h3)));
}

// ---------------------------------------------------------------------------
// Tensor-core NT GEMM, bf16x3, 4-stage cp.async pipeline, fused epilogues.
// MODE 0: C fp32 (output projection -> d_out)
// MODE 1: Q: rope * 0.125, split -> Ohi/Olo             (N = 2048)
// MODE 2: KV combined (N = 1024): col<512 -> rope -> K hi/lo; col>=512 -> V hi/lo
// ---------------------------------------------------------------------------
#define GSTG 40960           // bytes per stage (4 arrays * 128 rows * 80B)
#define GARR 10240
#define GSTAGES 4
#define GEMM_SMEM (GSTAGES * GSTG)   // 163840

template<int MODE>
__global__ __launch_bounds__(256) void gemm_bf16x3(
    const __nv_bfloat16* __restrict__ Ahi, const __nv_bfloat16* __restrict__ Alo,
    const __nv_bfloat16* __restrict__ Bhi, const __nv_bfloat16* __restrict__ Blo,
    float* __restrict__ C,
    __nv_bfloat16* __restrict__ Ohi, __nv_bfloat16* __restrict__ Olo,
    __nv_bfloat16* __restrict__ O2hi, __nv_bfloat16* __restrict__ O2lo,
    const float* __restrict__ fc, const float* __restrict__ fs,
    int M, int N, int K)
{
    extern __shared__ __align__(16) char smem_raw[];
    const uint32_t sbase = (uint32_t)__cvta_generic_to_shared(smem_raw);
    const int tid  = threadIdx.x;
    const int lane = tid & 31;
    const int warp = tid >> 5;
    const int wm   = warp >> 1;
    const int wn   = warp & 1;
    const int bm   = blockIdx.y * 128;
    const int bn   = blockIdx.x * 128;

    const __nv_bfloat16* gp[4] = {
        Ahi + (size_t)bm * K, Alo + (size_t)bm * K,
        Bhi + (size_t)bn * K, Blo + (size_t)bn * K };

    float c[2][8][4];
#pragma unroll
    for (int i = 0; i < 2; i++)
#pragma unroll
        for (int j = 0; j < 8; j++)
#pragma unroll
            for (int q = 0; q < 4; q++) c[i][j][q] = 0.0f;

    auto load_stage = [&](int stg, int k0) {
        uint32_t sb = sbase + stg * GSTG;
#pragma unroll
        for (int arr = 0; arr < 4; arr++) {
#pragma unroll
            for (int it = 0; it < 2; it++) {
                int idx = tid + it * 256;
                int row = idx >> 2;
                int c4  = idx & 3;
                const void* g = gp[arr] + (size_t)row * K + k0 + c4 * 8;
                uint32_t s = sb + arr * GARR + row * 80 + c4 * 16;
                CP_ASYNC16(s, g);
            }
        }
        asm volatile("cp.async.commit_group;");
    };

    const int KT = K >> 5;               // 64
#pragma unroll
    for (int s = 0; s < GSTAGES - 1; s++) load_stage(s, s * 32);

    for (int kt = 0; kt < KT; kt++) {
        asm volatile("cp.async.wait_group %0;" :: "n"(GSTAGES - 2));
        __syncthreads();
        if (kt + GSTAGES - 1 < KT)
            load_stage((kt + GSTAGES - 1) & (GSTAGES - 1), (kt + GSTAGES - 1) * 32);

        uint32_t sb = sbase + (kt & (GSTAGES - 1)) * GSTG;
#pragma unroll
        for (int s16 = 0; s16 < 2; s16++) {
            const int ko = s16 * 16;
            uint32_t a_hi[2][4], a_lo[2][4], b_hi[4][4], b_lo[4][4];
#pragma unroll
            for (int i = 0; i < 2; i++) {
                uint32_t ar = sb + (wm * 32 + i * 16 + (lane & 15)) * 80
                                 + (ko + (lane >> 4) * 8) * 2;
                ldm_x4(a_hi[i], ar);
                ldm_x4(a_lo[i], ar + GARR);
            }
            const int grp = lane >> 3, rr = lane & 7;
#pragma unroll
            for (int jp = 0; jp < 4; jp++) {
                int row = wn * 64 + jp * 16 + (grp >> 1) * 8 + rr;
                uint32_t br = sb + 2 * GARR + row * 80 + (ko + (grp & 1) * 8) * 2;
                ldm_x4(b_hi[jp], br);
                ldm_x4(b_lo[jp], br + GARR);
            }
#pragma unroll
            for (int i = 0; i < 2; i++)
#pragma unroll
                for (int j = 0; j < 8; j++) {
                    const int jp = j >> 1, off = (j & 1) * 2;
                    mma16816(c[i][j], a_hi[i], &b_hi[jp][off]);
                    mma16816(c[i][j], a_hi[i], &b_lo[jp][off]);
                    mma16816(c[i][j], a_lo[i], &b_hi[jp][off]);
                }
        }
    }

    // ---- epilogue ----
    const int rowb = bm + wm * 32 + (lane >> 2);
    const int colb = bn + wn * 64 + (lane & 3) * 2;

    if (MODE == 0) {
#pragma unroll
        for (int i = 0; i < 2; i++)
#pragma unroll
            for (int j = 0; j < 8; j++) {
                int row = rowb + i * 16;
                int col = colb + j * 8;
                *(float2*)&C[(size_t)row * N + col]       = make_float2(c[i][j][0], c[i][j][1]);
                *(float2*)&C[(size_t)(row + 8) * N + col] = make_float2(c[i][j][2], c[i][j][3]);
            }
    } else {
#pragma unroll
        for (int i = 0; i < 2; i++)
#pragma unroll
            for (int j = 0; j < 8; j++) {
                int col = colb + j * 8;
#pragma unroll
                for (int rr = 0; rr < 2; rr++) {
                    int row = rowb + i * 16 + rr * 8;
                    float v0 = c[i][j][rr * 2], v1 = c[i][j][rr * 2 + 1];
                    if (MODE == 1 || col < 512) {
                        int l = row & (L_ - 1);
                        int p = (col & 63) >> 1;
                        float cc = fc[l * 32 + p], ss = fs[l * 32 + p];
                        float sca = (MODE == 1) ? 0.125f : 1.0f;
                        float o0 = (v0 * cc - v1 * ss) * sca;
                        float o1 = (v0 * ss + v1 * cc) * sca;
                        v0 = o0; v1 = o1;
                    }
                    if (MODE == 1) {
                        split_store(Ohi, Olo, (size_t)row * N + col, v0, v1);
                    } else {
                        if (col < 512) split_store(Ohi,  Olo,  (size_t)row * 512 + col, v0, v1);
                        else           split_store(O2hi, O2lo, (size_t)row * 512 + col - 512, v0, v1);
                    }
                }
            }
    }
}

// ---------------------------------------------------------------------------
// Tensor-core causal GQA flash attention, bf16x3 (unchanged from round 4).
// ---------------------------------------------------------------------------
#define SROW 72
#define STG_HALVES 18432
#define ATTN_SMEM_BYTES ((9216 + 2 * STG_HALVES) * 2)   // 92160

__global__ __launch_bounds__(128) void attn_mma(
    const __nv_bfloat16* __restrict__ Qhi, const __nv_bfloat16* __restrict__ Qlo,
    const __nv_bfloat16* __restrict__ Khi, const __nv_bfloat16* __restrict__ Klo,
    const __nv_bfloat16* __restrict__ Vhi, const __nv_bfloat16* __restrict__ Vlo,
    __nv_bfloat16* __restrict__ Ohi, __nv_bfloat16* __restrict__ Olo)
{
    extern __shared__ __align__(16) char smem_raw[];
    const uint32_t sb = (uint32_t)__cvta_generic_to_shared(smem_raw);
    const int qb  = (int)(gridDim.x - 1 - blockIdx.x);
    const int h   = blockIdx.y;
    const int b   = blockIdx.z;
    const int kvh = h >> 2;
    const int tid  = threadIdx.x;
    const int lane = tid & 31;
    const int warp = tid >> 5;

    {
        const size_t qoff = ((size_t)(b * L_ + qb * 64) * H_ + h) * D_;
        const __nv_bfloat16* qs[2] = { Qhi + qoff, Qlo + qoff };
#pragma unroll
        for (int arr = 0; arr < 2; arr++)
#pragma unroll
            for (int it = 0; it < 4; it++) {
                int idx = tid + it * 128, row = idx >> 3, ch = idx & 7;
                uint32_t dst = sb + (arr * 4608 + row * SROW + ch * 8) * 2;
                const void* src = qs[arr] + (size_t)row * (H_ * D_) + ch * 8;
                CP_ASYNC16(dst, src);
            }
    }
    auto load_kv = [&](int stg, int kb) {
        const size_t koff = ((size_t)(b * L_ + kb * 64) * KVH_ + kvh) * D_;
        const __nv_bfloat16* srcs[4] = { Khi + koff, Klo + koff, Vhi + koff, Vlo + koff };
        uint32_t base = sb + (9216 + stg * STG_HALVES) * 2;
#pragma unroll
        for (int arr = 0; arr < 4; arr++)
#pragma unroll
            for (int it = 0; it < 4; it++) {
                int idx = tid + it * 128, row = idx >> 3, ch = idx & 7;
                uint32_t dst = base + (arr * 4608 + row * SROW + ch * 8) * 2;
                const void* src = srcs[arr] + (size_t)row * (KVH_ * D_) + ch * 8;
                CP_ASYNC16(dst, src);
            }
    };
    load_kv(0, 0);
    asm volatile("cp.async.commit_group;");

    float O[8][4];
#pragma unroll
    for (int nt = 0; nt < 8; nt++)
#pragma unroll
        for (int q = 0; q < 4; q++) O[nt][q] = 0.0f;
    float m0 = -1e30f, m1 = -1e30f, l0 = 0.0f, l1 = 0.0f;

    const int grp = lane >> 3;

    for (int kb = 0; kb <= qb; kb++) {
        if (kb < qb) {
            load_kv((kb + 1) & 1, kb + 1);
            asm volatile("cp.async.commit_group;");
            asm volatile("cp.async.wait_group 1;");
        } else {
            asm volatile("cp.async.wait_group 0;");
        }
        __syncthreads();

        const uint32_t stb = sb + (9216 + (kb & 1) * STG_HALVES) * 2;

        float sc[8][4];
#pragma unroll
        for (int nt = 0; nt < 8; nt++)
#pragma unroll
            for (int q = 0; q < 4; q++) sc[nt][q] = 0.0f;

#pragma unroll
        for (int ks = 0; ks < 4; ks++) {
            uint32_t ah[4], al[4];
            uint32_t qa = sb + ((warp * 16 + (lane & 15)) * SROW
                                + ks * 16 + (lane >> 4) * 8) * 2;
            ldm_x4(ah, qa);
            ldm_x4(al, qa + 9216);
#pragma unroll
            for (int jn = 0; jn < 4; jn++) {
                uint32_t ka = stb + ((jn * 16 + (grp >> 1) * 8 + (lane & 7)) * SROW
                                     + ks * 16 + (grp & 1) * 8) * 2;
                uint32_t bh[4], bl[4];
                ldm_x4(bh, ka);
                ldm_x4(bl, ka + 9216);
                mma16816(sc[2 * jn],     ah, &bh[0]);
                mma16816(sc[2 * jn],     ah, &bl[0]);
                mma16816(sc[2 * jn],     al, &bh[0]);
                mma16816(sc[2 * jn + 1], ah, &bh[2]);
                mma16816(sc[2 * jn + 1], ah, &bl[2]);
                mma16816(sc[2 * jn + 1], al, &bh[2]);
            }
        }

        const int r0g = qb * 64 + warp * 16 + (lane >> 2);
        if (kb == qb) {
            const int cb = kb * 64 + (lane & 3) * 2;
#pragma unroll
            for (int nt = 0; nt < 8; nt++) {
                int c = cb + nt * 8;
                if (c     > r0g)     sc[nt][0] = -1e30f;
                if (c + 1 > r0g)     sc[nt][1] = -1e30f;
                if (c     > r0g + 8) sc[nt][2] = -1e30f;
                if (c + 1 > r0g + 8) sc[nt][3] = -1e30f;
            }
        }

        float mx0 = sc[0][0], mx1 = sc[0][2];
#pragma unroll
        for (int nt = 0; nt < 8; nt++) {
            mx0 = fmaxf(mx0, fmaxf(sc[nt][0], sc[nt][1]));
            mx1 = fmaxf(mx1, fmaxf(sc[nt][2], sc[nt][3]));
        }
        mx0 = fmaxf(mx0, __shfl_xor_sync(0xffffffffu, mx0, 1));
        mx0 = fmaxf(mx0, __shfl_xor_sync(0xffffffffu, mx0, 2));
        mx1 = fmaxf(mx1, __shfl_xor_sync(0xffffffffu, mx1, 1));
        mx1 = fmaxf(mx1, __shfl_xor_sync(0xffffffffu, mx1, 2));
        float mn0 = fmaxf(m0, mx0), mn1 = fmaxf(m1, mx1);
        float a0 = __expf(m0 - mn0), a1 = __expf(m1 - mn1);
        m0 = mn0; m1 = mn1;
        float s0 = 0.0f, s1 = 0.0f;
#pragma unroll
        for (int nt = 0; nt < 8; nt++) {
            sc[nt][0] = __expf(sc[nt][0] - mn0);
            sc[nt][1] = __expf(sc[nt][1] - mn0);
            sc[nt][2] = __expf(sc[nt][2] - mn1);
            sc[nt][3] = __expf(sc[nt][3] - mn1);
            s0 += sc[nt][0] + sc[nt][1];
            s1 += sc[nt][2] + sc[nt][3];
        }
        s0 += __shfl_xor_sync(0xffffffffu, s0, 1);
        s0 += __shfl_xor_sync(0xffffffffu, s0, 2);
        s1 += __shfl_xor_sync(0xffffffffu, s1, 1);
        s1 += __shfl_xor_sync(0xffffffffu, s1, 2);
        l0 = l0 * a0 + s0;
        l1 = l1 * a1 + s1;
#pragma unroll
        for (int nt = 0; nt < 8; nt++) {
            O[nt][0] *= a0; O[nt][1] *= a0;
            O[nt][2] *= a1; O[nt][3] *= a1;
        }

#pragma unroll
        for (int ks = 0; ks < 4; ks++) {
            uint32_t ph[4], pl[4];
#pragma unroll
            for (int t = 0; t < 2; t++) {
                int nt = 2 * ks + t;
#pragma unroll
                for (int j = 0; j < 2; j++) {
                    float x0 = sc[nt][2 * j], x1 = sc[nt][2 * j + 1];
                    __nv_bfloat16 h0 = __float2bfloat16(x0);
                    __nv_bfloat16 h1 = __float2bfloat16(x1);
                    __nv_bfloat162 hp = __halves2bfloat162(h0, h1);
                    __nv_bfloat162 lp = __halves2bfloat162(
                        __float2bfloat16(x0 - __bfloat162float(h0)),
                        __float2bfloat16(x1 - __bfloat162float(h1)));
                    ph[t * 2 + j] = *(uint32_t*)&hp;
                    pl[t * 2 + j] = *(uint32_t*)&lp;
                }
            }
#pragma unroll
            for (int dj = 0; dj < 4; dj++) {
                uint32_t va = stb + 18432
                            + ((ks * 16 + (grp & 1) * 8 + (lane & 7)) * SROW
                               + dj * 16 + (grp >> 1) * 8) * 2;
                uint32_t vh[4], vl[4];
                ldm_x4_t(vh, va);
                ldm_x4_t(vl, va + 9216);
                mma16816(O[2 * dj],     ph, &vh[0]);
                mma16816(O[2 * dj],     ph, &vl[0]);
                mma16816(O[2 * dj],     pl, &vh[0]);
                mma16816(O[2 * dj + 1], ph, &vh[2]);
                mma16816(O[2 * dj + 1], ph, &vl[2]);
                mma16816(O[2 * dj + 1], pl, &vh[2]);
            }
        }
        __syncthreads();
    }

    float i0 = 1.0f / l0, i1 = 1.0f / l1;
    const size_t ro = ((size_t)(b * L_ + qb * 64 + warp * 16 + (lane >> 2)) * H_ + h) * D_
                      + (lane & 3) * 2;
    const size_t r8 = ro + (size_t)8 * H_ * D_;
#pragma unroll
    for (int nt = 0; nt < 8; nt++) {
        split_store(Ohi, Olo, ro + nt * 8, O[nt][0] * i0, O[nt][1] * i0);
        split_store(Ohi, Olo, r8 + nt * 8, O[nt][2] * i1, O[nt][3] * i1);
    }
}

// ---------------------------------------------------------------------------
// Launch
// ---------------------------------------------------------------------------
static inline void run_split(const float* src, __nv_bfloat16* hi, __nv_bfloat16* lo, size_t n)
{
    int n4 = (int)(n / 4);
    split_kernel<<<(n4 + 255) / 256, 256>>>(src, hi, lo, n4);
}

extern "C" void kernel_launch(void* const* d_in, const int* in_sizes, int n_in,
                              void* d_out, int out_size)
{
    const float* x  = (const float*)d_in[0];
    const float* wq = (const float*)d_in[1];
    const float* wk = (const float*)d_in[2];
    const float* wv = (const float*)d_in[3];
    const float* wo = (const float*)d_in[4];
    const float* fc = (const float*)d_in[5];
    const float* fs = (const float*)d_in[6];
    float* out = (float*)d_out;

    __nv_bfloat16 *xhi, *xlo, *wqhi, *wqlo, *wkvhi, *wkvlo, *wohi, *wolo;
    __nv_bfloat16 *ahi, *alo, *qhi, *qlo, *khi, *klo, *vhi, *vlo;
    cudaGetSymbolAddress((void**)&xhi,   g_xhi);   cudaGetSymbolAddress((void**)&xlo,   g_xlo);
    cudaGetSymbolAddress((void**)&wqhi,  g_wqhi);  cudaGetSymbolAddress((void**)&wqlo,  g_wqlo);
    cudaGetSymbolAddress((void**)&wkvhi, g_wkvhi); cudaGetSymbolAddress((void**)&wkvlo, g_wkvlo);
    cudaGetSymbolAddress((void**)&wohi,  g_wohi);  cudaGetSymbolAddress((void**)&wolo,  g_wolo);
    cudaGetSymbolAddress((void**)&ahi,   g_ahi);   cudaGetSymbolAddress((void**)&alo,   g_alo);
    cudaGetSymbolAddress((void**)&qhi,   g_qhi);   cudaGetSymbolAddress((void**)&qlo,   g_qlo);
    cudaGetSymbolAddress((void**)&khi,   g_khi);   cudaGetSymbolAddress((void**)&klo,   g_klo);
    cudaGetSymbolAddress((void**)&vhi,   g_vhi);   cudaGetSymbolAddress((void**)&vlo,   g_vlo);

    const int M = B_ * L_;                       // 4096

    cudaFuncSetAttribute(gemm_bf16x3<0>, cudaFuncAttributeMaxDynamicSharedMemorySize, GEMM_SMEM);
    cudaFuncSetAttribute(gemm_bf16x3<1>, cudaFuncAttributeMaxDynamicSharedMemorySize, GEMM_SMEM);
    cudaFuncSetAttribute(gemm_bf16x3<2>, cudaFuncAttributeMaxDynamicSharedMemorySize, GEMM_SMEM);
    cudaFuncSetAttribute(attn_mma, cudaFuncAttributeMaxDynamicSharedMemorySize, ATTN_SMEM_BYTES);

    // Splits: x, wq, wk->wkv[0:512], wv->wkv[512:1024], wo
    run_split(x,  xhi,  xlo,  NX);
    run_split(wq, wqhi, wqlo, NWQ);
    run_split(wk, wkvhi,                wkvlo,                NWK);
    run_split(wv, wkvhi + NWK,          wkvlo + NWK,          NWK);
    run_split(wo, wohi, wolo, NWO);

    // Q projection with fused rope+scale+split epilogue
    gemm_bf16x3<1><<<dim3((H_ * D_) / 128, M / 128), 256, GEMM_SMEM>>>(
        xhi, xlo, wqhi, wqlo, nullptr, qhi, qlo, nullptr, nullptr, fc, fs,
        M, H_ * D_, HID_);

    // K+V combined projection: rope+split K, split V
    gemm_bf16x3<2><<<dim3(1024 / 128, M / 128), 256, GEMM_SMEM>>>(
        xhi, xlo, wkvhi, wkvlo, nullptr, khi, klo, vhi, vlo, fc, fs,
        M, 1024, HID_);

    // Attention (tensor cores, bf16x3)
    attn_mma<<<dim3(L_ / 64, H_, B_), 128, ATTN_SMEM_BYTES>>>(
        qhi, qlo, khi, klo, vhi, vlo, ahi, alo);

    // Output projection -> d_out (fp32)
    gemm_bf16x3<0><<<dim3(HID_ / 128, M / 128), 256, GEMM_SMEM>>>(
        ahi, alo, wohi, wolo, out, nullptr, nullptr, nullptr, nullptr, nullptr, nullptr,
        M, HID_, H_ * D_);
}

// round 8
// speedup vs baseline: 3.1346x; 1.1775x over previous
#include <cuda_runtime.h>
#include <cuda_bf16.h>
#include <cstdint>

// Problem constants
#define B_   2
#define L_   2048
#define HID_ 2048
#define H_   32
#define KVH_ 8
#define D_   64

#define NX  ((size_t)B_ * L_ * HID_)
#define NQ  ((size_t)B_ * L_ * H_ * D_)
#define NKV ((size_t)B_ * L_ * KVH_ * D_)
#define NWQ ((size_t)H_ * D_ * HID_)
#define NWK ((size_t)KVH_ * D_ * HID_)
#define NWO ((size_t)HID_ * H_ * D_)

__device__ __nv_bfloat16 g_xhi  [NX],      g_xlo  [NX];
__device__ __nv_bfloat16 g_wqhi [NWQ],     g_wqlo [NWQ];
__device__ __nv_bfloat16 g_wkvhi[2 * NWK], g_wkvlo[2 * NWK];   // wk rows then wv rows
__device__ __nv_bfloat16 g_wohi [NWO],     g_wolo [NWO];
__device__ __nv_bfloat16 g_ahi  [NX],      g_alo  [NX];
__device__ __nv_bfloat16 g_qhi  [NQ],      g_qlo  [NQ];
__device__ __nv_bfloat16 g_khi  [NKV],     g_klo  [NKV];
__device__ __nv_bfloat16 g_vhi  [NKV],     g_vlo  [NKV];

// ---------------------------------------------------------------------------
// PTX helpers (legacy mma path only — sm_100 base target has no tcgen05)
// ---------------------------------------------------------------------------
__device__ __forceinline__ void ldm_x4(uint32_t* r, uint32_t addr) {
    asm volatile("ldmatrix.sync.aligned.m8n8.x4.shared.b16 {%0,%1,%2,%3}, [%4];"
                 : "=r"(r[0]), "=r"(r[1]), "=r"(r[2]), "=r"(r[3]) : "r"(addr));
}
__device__ __forceinline__ void ldm_x4_t(uint32_t* r, uint32_t addr) {
    asm volatile("ldmatrix.sync.aligned.m8n8.x4.trans.shared.b16 {%0,%1,%2,%3}, [%4];"
                 : "=r"(r[0]), "=r"(r[1]), "=r"(r[2]), "=r"(r[3]) : "r"(addr));
}
__device__ __forceinline__ void mma16816(float* d, const uint32_t* a, const uint32_t* b) {
    asm volatile("mma.sync.aligned.m16n8k16.row.col.f32.bf16.bf16.f32 "
                 "{%0,%1,%2,%3}, {%4,%5,%6,%7}, {%8,%9}, {%0,%1,%2,%3};"
                 : "+f"(d[0]), "+f"(d[1]), "+f"(d[2]), "+f"(d[3])
                 : "r"(a[0]), "r"(a[1]), "r"(a[2]), "r"(a[3]), "r"(b[0]), "r"(b[1]));
}
#define CP_ASYNC16(dst, src) \
    asm volatile("cp.async.cg.shared.global [%0], [%1], 16;" :: "r"(dst), "l"(src))

__device__ __forceinline__ void split_store(__nv_bfloat16* hi, __nv_bfloat16* lo,
                                            size_t idx, float v0, float v1)
{
    __nv_bfloat16 h0 = __float2bfloat16(v0), h1 = __float2bfloat16(v1);
    *(__nv_bfloat162*)(hi + idx) = __halves2bfloat162(h0, h1);
    *(__nv_bfloat162*)(lo + idx) = __halves2bfloat162(
        __float2bfloat16(v0 - __bfloat162float(h0)),
        __float2bfloat16(v1 - __bfloat162float(h1)));
}

// ---------------------------------------------------------------------------
// Split fp32 -> bf16 hi + bf16 lo
// ---------------------------------------------------------------------------
__global__ void split_kernel(const float* __restrict__ in,
                             __nv_bfloat16* __restrict__ hi,
                             __nv_bfloat16* __restrict__ lo, int n4)
{
    int i = blockIdx.x * blockDim.x + threadIdx.x;
    if (i >= n4) return;
    float4 v = ((const float4*)in)[i];
    __nv_bfloat16 h0 = __float2bfloat16(v.x);
    __nv_bfloat16 h1 = __float2bfloat16(v.y);
    __nv_bfloat16 h2 = __float2bfloat16(v.z);
    __nv_bfloat16 h3 = __float2bfloat16(v.w);
    ((__nv_bfloat162*)hi)[2 * i + 0] = __halves2bfloat162(h0, h1);
    ((__nv_bfloat162*)hi)[2 * i + 1] = __halves2bfloat162(h2, h3);
    ((__nv_bfloat162*)lo)[2 * i + 0] = __halves2bfloat162(
        __float2bfloat16(v.x - __bfloat162float(h0)),
        __float2bfloat16(v.y - __bfloat162float(h1)));
    ((__nv_bfloat162*)lo)[2 * i + 1] = __halves2bfloat162(
        __float2bfloat16(v.z - __bfloat162float(h2)),
        __float2bfloat16(v.w - __bfloat162float(h3)));
}

// ---------------------------------------------------------------------------
// Tensor-core NT GEMM, bf16x3:
//   C = Ahi*Bhi^T + Ahi*Blo^T + Alo*Bhi^T  (fp32 accumulate)
// CTA tile 64x128, 128 threads (4 warps as 2x2, warp tile 32x64), BK=32,
// 2-stage cp.async, 80B-padded rows. 3 CTAs/SM for latency hiding.
// MODE 0: fp32 C out;  MODE 1: rope*0.125 -> Ohi/Olo (N=2048);
// MODE 2: col<512 rope -> Ohi/Olo(K), col>=512 -> O2hi/O2lo(V)
// ---------------------------------------------------------------------------
#define GA_HI 0
#define GA_LO 5120
#define GB_HI 10240
#define GB_LO 20480
#define GSTG  30720
#define GEMM_SMEM (2 * GSTG)    // 61440

template<int MODE>
__global__ __launch_bounds__(128, 3) void gemm_bf16x3(
    const __nv_bfloat16* __restrict__ Ahi, const __nv_bfloat16* __restrict__ Alo,
    const __nv_bfloat16* __restrict__ Bhi, const __nv_bfloat16* __restrict__ Blo,
    float* __restrict__ C,
    __nv_bfloat16* __restrict__ Ohi, __nv_bfloat16* __restrict__ Olo,
    __nv_bfloat16* __restrict__ O2hi, __nv_bfloat16* __restrict__ O2lo,
    const float* __restrict__ fc, const float* __restrict__ fs,
    int M, int N, int K)
{
    extern __shared__ __align__(16) char smem_raw[];
    const uint32_t sbase = (uint32_t)__cvta_generic_to_shared(smem_raw);
    const int tid  = threadIdx.x;
    const int lane = tid & 31;
    const int warp = tid >> 5;
    const int wm   = warp & 1;           // m offset wm*32
    const int wn   = warp >> 1;          // n offset wn*64
    const int bm   = blockIdx.y * 64;
    const int bn   = blockIdx.x * 128;

    const __nv_bfloat16* gA[2] = { Ahi + (size_t)bm * K, Alo + (size_t)bm * K };
    const __nv_bfloat16* gB[2] = { Bhi + (size_t)bn * K, Blo + (size_t)bn * K };

    float c[2][8][4];
#pragma unroll
    for (int i = 0; i < 2; i++)
#pragma unroll
        for (int j = 0; j < 8; j++)
#pragma unroll
            for (int q = 0; q < 4; q++) c[i][j][q] = 0.0f;

    auto load_stage = [&](int stg, int k0) {
        uint32_t sb = sbase + stg * GSTG;
        // A arrays: 64 rows x 4 chunks = 256 chunks -> 2 iters
#pragma unroll
        for (int arr = 0; arr < 2; arr++)
#pragma unroll
            for (int it = 0; it < 2; it++) {
                int idx = tid + it * 128;
                int row = idx >> 2, c4 = idx & 3;
                const void* g = gA[arr] + (size_t)row * K + k0 + c4 * 8;
                CP_ASYNC16(sb + (arr ? GA_LO : GA_HI) + row * 80 + c4 * 16, g);
            }
        // B arrays: 128 rows x 4 chunks = 512 chunks -> 4 iters
#pragma unroll
        for (int arr = 0; arr < 2; arr++)
#pragma unroll
            for (int it = 0; it < 4; it++) {
                int idx = tid + it * 128;
                int row = idx >> 2, c4 = idx & 3;
                const void* g = gB[arr] + (size_t)row * K + k0 + c4 * 8;
                CP_ASYNC16(sb + (arr ? GB_LO : GB_HI) + row * 80 + c4 * 16, g);
            }
        asm volatile("cp.async.commit_group;");
    };

    load_stage(0, 0);
    const int KT = K >> 5;
    for (int kt = 0; kt < KT; kt++) {
        if (kt + 1 < KT) {
            load_stage((kt + 1) & 1, (kt + 1) * 32);
            asm volatile("cp.async.wait_group 1;");
        } else {
            asm volatile("cp.async.wait_group 0;");
        }
        __syncthreads();

        uint32_t sb = sbase + (kt & 1) * GSTG;
#pragma unroll
        for (int s16 = 0; s16 < 2; s16++) {
            const int ko = s16 * 16;
            uint32_t a_hi[2][4], a_lo[2][4], b_hi[4][4], b_lo[4][4];
#pragma unroll
            for (int i = 0; i < 2; i++) {
                uint32_t ar = sb + GA_HI + (wm * 32 + i * 16 + (lane & 15)) * 80
                                 + (ko + (lane >> 4) * 8) * 2;
                ldm_x4(a_hi[i], ar);
                ldm_x4(a_lo[i], ar + (GA_LO - GA_HI));
            }
            const int grp = lane >> 3, rr = lane & 7;
#pragma unroll
            for (int jp = 0; jp < 4; jp++) {
                int row = wn * 64 + jp * 16 + (grp >> 1) * 8 + rr;
                uint32_t br = sb + GB_HI + row * 80 + (ko + (grp & 1) * 8) * 2;
                ldm_x4(b_hi[jp], br);
                ldm_x4(b_lo[jp], br + (GB_LO - GB_HI));
            }
#pragma unroll
            for (int i = 0; i < 2; i++)
#pragma unroll
                for (int j = 0; j < 8; j++) {
                    const int jp = j >> 1, off = (j & 1) * 2;
                    mma16816(c[i][j], a_hi[i], &b_hi[jp][off]);
                    mma16816(c[i][j], a_hi[i], &b_lo[jp][off]);
                    mma16816(c[i][j], a_lo[i], &b_hi[jp][off]);
                }
        }
        __syncthreads();
    }

    // ---- epilogue ----
    const int rowb = bm + wm * 32 + (lane >> 2);
    const int colb = bn + wn * 64 + (lane & 3) * 2;

    if (MODE == 0) {
#pragma unroll
        for (int i = 0; i < 2; i++)
#pragma unroll
            for (int j = 0; j < 8; j++) {
                int row = rowb + i * 16;
                int col = colb + j * 8;
                *(float2*)&C[(size_t)row * N + col]       = make_float2(c[i][j][0], c[i][j][1]);
                *(float2*)&C[(size_t)(row + 8) * N + col] = make_float2(c[i][j][2], c[i][j][3]);
            }
    } else {
#pragma unroll
        for (int i = 0; i < 2; i++)
#pragma unroll
            for (int j = 0; j < 8; j++) {
                int col = colb + j * 8;
#pragma unroll
                for (int rr2 = 0; rr2 < 2; rr2++) {
                    int row = rowb + i * 16 + rr2 * 8;
                    float v0 = c[i][j][rr2 * 2], v1 = c[i][j][rr2 * 2 + 1];
                    if (MODE == 1 || col < 512) {
                        int l = row & (L_ - 1);
                        int p = (col & 63) >> 1;
                        float cc = fc[l * 32 + p], ss = fs[l * 32 + p];
                        float sca = (MODE == 1) ? 0.125f : 1.0f;
                        float o0 = (v0 * cc - v1 * ss) * sca;
                        float o1 = (v0 * ss + v1 * cc) * sca;
                        v0 = o0; v1 = o1;
                    }
                    if (MODE == 1) {
                        split_store(Ohi, Olo, (size_t)row * N + col, v0, v1);
                    } else {
                        if (col < 512) split_store(Ohi,  Olo,  (size_t)row * 512 + col, v0, v1);
                        else           split_store(O2hi, O2lo, (size_t)row * 512 + col - 512, v0, v1);
                    }
                }
            }
    }
}

// ---------------------------------------------------------------------------
// Tensor-core causal GQA flash attention, bf16x3 (unchanged — proven).
// ---------------------------------------------------------------------------
#define SROW 72
#define STG_HALVES 18432
#define ATTN_SMEM_BYTES ((9216 + 2 * STG_HALVES) * 2)   // 92160

__global__ __launch_bounds__(128) void attn_mma(
    const __nv_bfloat16* __restrict__ Qhi, const __nv_bfloat16* __restrict__ Qlo,
    const __nv_bfloat16* __restrict__ Khi, const __nv_bfloat16* __restrict__ Klo,
    const __nv_bfloat16* __restrict__ Vhi, const __nv_bfloat16* __restrict__ Vlo,
    __nv_bfloat16* __restrict__ Ohi, __nv_bfloat16* __restrict__ Olo)
{
    extern __shared__ __align__(16) char smem_raw[];
    const uint32_t sb = (uint32_t)__cvta_generic_to_shared(smem_raw);
    const int qb  = (int)(gridDim.x - 1 - blockIdx.x);
    const int h   = blockIdx.y;
    const int b   = blockIdx.z;
    const int kvh = h >> 2;
    const int tid  = threadIdx.x;
    const int lane = tid & 31;
    const int warp = tid >> 5;

    {
        const size_t qoff = ((size_t)(b * L_ + qb * 64) * H_ + h) * D_;
        const __nv_bfloat16* qs[2] = { Qhi + qoff, Qlo + qoff };
#pragma unroll
        for (int arr = 0; arr < 2; arr++)
#pragma unroll
            for (int it = 0; it < 4; it++) {
                int idx = tid + it * 128, row = idx >> 3, ch = idx & 7;
                uint32_t dst = sb + (arr * 4608 + row * SROW + ch * 8) * 2;
                const void* src = qs[arr] + (size_t)row * (H_ * D_) + ch * 8;
                CP_ASYNC16(dst, src);
            }
    }
    auto load_kv = [&](int stg, int kb) {
        const size_t koff = ((size_t)(b * L_ + kb * 64) * KVH_ + kvh) * D_;
        const __nv_bfloat16* srcs[4] = { Khi + koff, Klo + koff, Vhi + koff, Vlo + koff };
        uint32_t base = sb + (9216 + stg * STG_HALVES) * 2;
#pragma unroll
        for (int arr = 0; arr < 4; arr++)
#pragma unroll
            for (int it = 0; it < 4; it++) {
                int idx = tid + it * 128, row = idx >> 3, ch = idx & 7;
                uint32_t dst = base + (arr * 4608 + row * SROW + ch * 8) * 2;
                const void* src = srcs[arr] + (size_t)row * (KVH_ * D_) + ch * 8;
                CP_ASYNC16(dst, src);
            }
    };
    load_kv(0, 0);
    asm volatile("cp.async.commit_group;");

    float O[8][4];
#pragma unroll
    for (int nt = 0; nt < 8; nt++)
#pragma unroll
        for (int q = 0; q < 4; q++) O[nt][q] = 0.0f;
    float m0 = -1e30f, m1 = -1e30f, l0 = 0.0f, l1 = 0.0f;

    const int grp = lane >> 3;

    for (int kb = 0; kb <= qb; kb++) {
        if (kb < qb) {
            load_kv((kb + 1) & 1, kb + 1);
            asm volatile("cp.async.commit_group;");
            asm volatile("cp.async.wait_group 1;");
        } else {
            asm volatile("cp.async.wait_group 0;");
        }
        __syncthreads();

        const uint32_t stb = sb + (9216 + (kb & 1) * STG_HALVES) * 2;

        float sc[8][4];
#pragma unroll
        for (int nt = 0; nt < 8; nt++)
#pragma unroll
            for (int q = 0; q < 4; q++) sc[nt][q] = 0.0f;

#pragma unroll
        for (int ks = 0; ks < 4; ks++) {
            uint32_t ah[4], al[4];
            uint32_t qa = sb + ((warp * 16 + (lane & 15)) * SROW
                                + ks * 16 + (lane >> 4) * 8) * 2;
            ldm_x4(ah, qa);
            ldm_x4(al, qa + 9216);
#pragma unroll
            for (int jn = 0; jn < 4; jn++) {
                uint32_t ka = stb + ((jn * 16 + (grp >> 1) * 8 + (lane & 7)) * SROW
                                     + ks * 16 + (grp & 1) * 8) * 2;
                uint32_t bh[4], bl[4];
                ldm_x4(bh, ka);
                ldm_x4(bl, ka + 9216);
                mma16816(sc[2 * jn],     ah, &bh[0]);
                mma16816(sc[2 * jn],     ah, &bl[0]);
                mma16816(sc[2 * jn],     al, &bh[0]);
                mma16816(sc[2 * jn + 1], ah, &bh[2]);
                mma16816(sc[2 * jn + 1], ah, &bl[2]);
                mma16816(sc[2 * jn + 1], al, &bh[2]);
            }
        }

        const int r0g = qb * 64 + warp * 16 + (lane >> 2);
        if (kb == qb) {
            const int cb = kb * 64 + (lane & 3) * 2;
#pragma unroll
            for (int nt = 0; nt < 8; nt++) {
                int c = cb + nt * 8;
                if (c     > r0g)     sc[nt][0] = -1e30f;
                if (c + 1 > r0g)     sc[nt][1] = -1e30f;
                if (c     > r0g + 8) sc[nt][2] = -1e30f;
                if (c + 1 > r0g + 8) sc[nt][3] = -1e30f;
            }
        }

        float mx0 = sc[0][0], mx1 = sc[0][2];
#pragma unroll
        for (int nt = 0; nt < 8; nt++) {
            mx0 = fmaxf(mx0, fmaxf(sc[nt][0], sc[nt][1]));
            mx1 = fmaxf(mx1, fmaxf(sc[nt][2], sc[nt][3]));
        }
        mx0 = fmaxf(mx0, __shfl_xor_sync(0xffffffffu, mx0, 1));
        mx0 = fmaxf(mx0, __shfl_xor_sync(0xffffffffu, mx0, 2));
        mx1 = fmaxf(mx1, __shfl_xor_sync(0xffffffffu, mx1, 1));
        mx1 = fmaxf(mx1, __shfl_xor_sync(0xffffffffu, mx1, 2));
        float mn0 = fmaxf(m0, mx0), mn1 = fmaxf(m1, mx1);
        float a0 = __expf(m0 - mn0), a1 = __expf(m1 - mn1);
        m0 = mn0; m1 = mn1;
        float s0 = 0.0f, s1 = 0.0f;
#pragma unroll
        for (int nt = 0; nt < 8; nt++) {
            sc[nt][0] = __expf(sc[nt][0] - mn0);
            sc[nt][1] = __expf(sc[nt][1] - mn0);
            sc[nt][2] = __expf(sc[nt][2] - mn1);
            sc[nt][3] = __expf(sc[nt][3] - mn1);
            s0 += sc[nt][0] + sc[nt][1];
            s1 += sc[nt][2] + sc[nt][3];
        }
        s0 += __shfl_xor_sync(0xffffffffu, s0, 1);
        s0 += __shfl_xor_sync(0xffffffffu, s0, 2);
        s1 += __shfl_xor_sync(0xffffffffu, s1, 1);
        s1 += __shfl_xor_sync(0xffffffffu, s1, 2);
        l0 = l0 * a0 + s0;
        l1 = l1 * a1 + s1;
#pragma unroll
        for (int nt = 0; nt < 8; nt++) {
            O[nt][0] *= a0; O[nt][1] *= a0;
            O[nt][2] *= a1; O[nt][3] *= a1;
        }

#pragma unroll
        for (int ks = 0; ks < 4; ks++) {
            uint32_t ph[4], pl[4];
#pragma unroll
            for (int t = 0; t < 2; t++) {
                int nt = 2 * ks + t;
#pragma unroll
                for (int j = 0; j < 2; j++) {
                    float x0 = sc[nt][2 * j], x1 = sc[nt][2 * j + 1];
                    __nv_bfloat16 h0 = __float2bfloat16(x0);
                    __nv_bfloat16 h1 = __float2bfloat16(x1);
                    __nv_bfloat162 hp = __halves2bfloat162(h0, h1);
                    __nv_bfloat162 lp = __halves2bfloat162(
                        __float2bfloat16(x0 - __bfloat162float(h0)),
                        __float2bfloat16(x1 - __bfloat162float(h1)));
                    ph[t * 2 + j] = *(uint32_t*)&hp;
                    pl[t * 2 + j] = *(uint32_t*)&lp;
                }
            }
#pragma unroll
            for (int dj = 0; dj < 4; dj++) {
                uint32_t va = stb + 18432
                            + ((ks * 16 + (grp & 1) * 8 + (lane & 7)) * SROW
                               + dj * 16 + (grp >> 1) * 8) * 2;
                uint32_t vh[4], vl[4];
                ldm_x4_t(vh, va);
                ldm_x4_t(vl, va + 9216);
                mma16816(O[2 * dj],     ph, &vh[0]);
                mma16816(O[2 * dj],     ph, &vl[0]);
                mma16816(O[2 * dj],     pl, &vh[0]);
                mma16816(O[2 * dj + 1], ph, &vh[2]);
                mma16816(O[2 * dj + 1], ph, &vl[2]);
                mma16816(O[2 * dj + 1], pl, &vh[2]);
            }
        }
        __syncthreads();
    }

    float i0 = 1.0f / l0, i1 = 1.0f / l1;
    const size_t ro = ((size_t)(b * L_ + qb * 64 + warp * 16 + (lane >> 2)) * H_ + h) * D_
                      + (lane & 3) * 2;
    const size_t r8 = ro + (size_t)8 * H_ * D_;
#pragma unroll
    for (int nt = 0; nt < 8; nt++) {
        split_store(Ohi, Olo, ro + nt * 8, O[nt][0] * i0, O[nt][1] * i0);
        split_store(Ohi, Olo, r8 + nt * 8, O[nt][2] * i1, O[nt][3] * i1);
    }
}

// ---------------------------------------------------------------------------
// Launch
// ---------------------------------------------------------------------------
static inline void run_split(const float* src, __nv_bfloat16* hi, __nv_bfloat16* lo, size_t n)
{
    int n4 = (int)(n / 4);
    split_kernel<<<(n4 + 255) / 256, 256>>>(src, hi, lo, n4);
}

extern "C" void kernel_launch(void* const* d_in, const int* in_sizes, int n_in,
                              void* d_out, int out_size)
{
    const float* x  = (const float*)d_in[0];
    const float* wq = (const float*)d_in[1];
    const float* wk = (const float*)d_in[2];
    const float* wv = (const float*)d_in[3];
    const float* wo = (const float*)d_in[4];
    const float* fc = (const float*)d_in[5];
    const float* fs = (const float*)d_in[6];
    float* out = (float*)d_out;

    __nv_bfloat16 *xhi, *xlo, *wqhi, *wqlo, *wkvhi, *wkvlo, *wohi, *wolo;
    __nv_bfloat16 *ahi, *alo, *qhi, *qlo, *khi, *klo, *vhi, *vlo;
    cudaGetSymbolAddress((void**)&xhi,   g_xhi);   cudaGetSymbolAddress((void**)&xlo,   g_xlo);
    cudaGetSymbolAddress((void**)&wqhi,  g_wqhi);  cudaGetSymbolAddress((void**)&wqlo,  g_wqlo);
    cudaGetSymbolAddress((void**)&wkvhi, g_wkvhi); cudaGetSymbolAddress((void**)&wkvlo, g_wkvlo);
    cudaGetSymbolAddress((void**)&wohi,  g_wohi);  cudaGetSymbolAddress((void**)&wolo,  g_wolo);
    cudaGetSymbolAddress((void**)&ahi,   g_ahi);   cudaGetSymbolAddress((void**)&alo,   g_alo);
    cudaGetSymbolAddress((void**)&qhi,   g_qhi);   cudaGetSymbolAddress((void**)&qlo,   g_qlo);
    cudaGetSymbolAddress((void**)&khi,   g_khi);   cudaGetSymbolAddress((void**)&klo,   g_klo);
    cudaGetSymbolAddress((void**)&vhi,   g_vhi);   cudaGetSymbolAddress((void**)&vlo,   g_vlo);

    const int M = B_ * L_;                       // 4096

    cudaFuncSetAttribute(gemm_bf16x3<0>, cudaFuncAttributeMaxDynamicSharedMemorySize, GEMM_SMEM);
    cudaFuncSetAttribute(gemm_bf16x3<1>, cudaFuncAttributeMaxDynamicSharedMemorySize, GEMM_SMEM);
    cudaFuncSetAttribute(gemm_bf16x3<2>, cudaFuncAttributeMaxDynamicSharedMemorySize, GEMM_SMEM);
    cudaFuncSetAttribute(attn_mma, cudaFuncAttributeMaxDynamicSharedMemorySize, ATTN_SMEM_BYTES);

    // Splits: x, wq, wk->wkv[0:512], wv->wkv[512:1024], wo
    run_split(x,  xhi,  xlo,  NX);
    run_split(wq, wqhi, wqlo, NWQ);
    run_split(wk, wkvhi,       wkvlo,       NWK);
    run_split(wv, wkvhi + NWK, wkvlo + NWK, NWK);
    run_split(wo, wohi, wolo, NWO);

    // Q projection, fused rope+scale+split epilogue
    gemm_bf16x3<1><<<dim3((H_ * D_) / 128, M / 64), 128, GEMM_SMEM>>>(
        xhi, xlo, wqhi, wqlo, nullptr, qhi, qlo, nullptr, nullptr, fc, fs,
        M, H_ * D_, HID_);

    // K+V combined projection: rope+split K, split V
    gemm_bf16x3<2><<<dim3(1024 / 128, M / 64), 128, GEMM_SMEM>>>(
        xhi, xlo, wkvhi, wkvlo, nullptr, khi, klo, vhi, vlo, fc, fs,
        M, 1024, HID_);

    // Attention (tensor cores, bf16x3)
    attn_mma<<<dim3(L_ / 64, H_, B_), 128, ATTN_SMEM_BYTES>>>(
        qhi, qlo, khi, klo, vhi, vlo, ahi, alo);

    // Output projection -> d_out (fp32)
    gemm_bf16x3<0><<<dim3(HID_ / 128, M / 64), 128, GEMM_SMEM>>>(
        ahi, alo, wohi, wolo, out, nullptr, nullptr, nullptr, nullptr, nullptr, nullptr,
        M, HID_, H_ * D_);
}